// round 11
// baseline (speedup 1.0000x reference)
#include <cuda_runtime.h>
#include <cuda_fp16.h>
#include <math.h>
#include <stdint.h>

#define Bsz   8
#define Tlen  1024
#define Cdim  768
#define Hn    12
#define Dh    64
#define BT    (Bsz * Tlen)     // 8192
#define C3    (3 * Cdim)       // 2304
#define BH    (Bsz * Hn)       // 96
#define Kdim  768

// ---------------- scratch (device globals; no cudaMalloc allowed) ----------
__device__ float g_qkv[BT * C3];

__device__ __half g_xh[BT * Cdim];
__device__ __half g_xm[BT * Cdim];
__device__ __half g_wah[C3 * Cdim];
__device__ __half g_wph[Cdim * Cdim];

__device__ __half g_qh[BH * Tlen * Dh];
__device__ __half g_qm[BH * Tlen * Dh];
__device__ __half g_kh[BH * Tlen * Dh];
__device__ __half g_km[BH * Tlen * Dh];
__device__ __half g_vh[BH * Tlen * Dh];

__device__ __half g_yh[BT * Cdim];
__device__ __half g_ym[BT * Cdim];

// ---------------- PTX helpers ----------------------------------------------
__device__ __forceinline__ uint32_t smem_u32(const void* p) {
    uint32_t a;
    asm("{ .reg .u64 t; cvta.to.shared.u64 t, %1; cvt.u32.u64 %0, t; }"
        : "=r"(a) : "l"(p));
    return a;
}
__device__ __forceinline__ void cpasync16(uint32_t dst, const void* src) {
    asm volatile("cp.async.cg.shared.global [%0], [%1], 16;\n" :: "r"(dst), "l"(src));
}
__device__ __forceinline__ void cp_commit() {
    asm volatile("cp.async.commit_group;\n" ::: "memory");
}
__device__ __forceinline__ void cp_wait1() {
    asm volatile("cp.async.wait_group 1;\n" ::: "memory");
}
__device__ __forceinline__ void cp_wait0() {
    asm volatile("cp.async.wait_group 0;\n" ::: "memory");
}
__device__ __forceinline__ void ldsm4(uint32_t (&r)[4], uint32_t addr) {
    asm volatile("ldmatrix.sync.aligned.m8n8.x4.shared.b16 {%0,%1,%2,%3}, [%4];"
        : "=r"(r[0]), "=r"(r[1]), "=r"(r[2]), "=r"(r[3]) : "r"(addr));
}
__device__ __forceinline__ void ldsm4t(uint32_t (&r)[4], uint32_t addr) {
    asm volatile("ldmatrix.sync.aligned.m8n8.x4.trans.shared.b16 {%0,%1,%2,%3}, [%4];"
        : "=r"(r[0]), "=r"(r[1]), "=r"(r[2]), "=r"(r[3]) : "r"(addr));
}
__device__ __forceinline__ void mma_f16(float (&c)[4], const uint32_t (&a)[4],
                                        uint32_t b0, uint32_t b1) {
    asm volatile(
        "mma.sync.aligned.m16n8k16.row.col.f32.f16.f16.f32 "
        "{%0,%1,%2,%3}, {%4,%5,%6,%7}, {%8,%9}, {%0,%1,%2,%3};"
        : "+f"(c[0]), "+f"(c[1]), "+f"(c[2]), "+f"(c[3])
        : "r"(a[0]), "r"(a[1]), "r"(a[2]), "r"(a[3]), "r"(b0), "r"(b1));
}
__device__ __forceinline__ float ex2(float x) {
    float y;
    asm("ex2.approx.f32 %0, %1;" : "=f"(y) : "f"(x));
    return y;
}
__device__ __forceinline__ void pack_hm(float p0, float p1, uint32_t& hi, uint32_t& mid) {
    __half2 h = __floats2half2_rn(p0, p1);
    float r0 = p0 - __half2float(__low2half(h));
    float r1 = p1 - __half2float(__high2half(h));
    __half2 m = __floats2half2_rn(r0, r1);
    hi  = *(uint32_t*)&h;
    mid = *(uint32_t*)&m;
}
__device__ __forceinline__ uint32_t pack_h(float p0, float p1) {
    __half2 h = __floats2half2_rn(p0, p1);
    return *(uint32_t*)&h;
}

#define QSCALE (0.125f * 1.4426950408889634f)

// ---------------------------------------------------------------------------
// fp16x2 GEMM v2: C = (Ah + Am) @ Bh^T + bias, 2 passes.
// CTA 128x128, 8 warps (2x4, warp tile 64x32), K-tile 32, 3-stage ring,
// one sync/iter, 2 CTAs/SM (16 warps/SM).
// ---------------------------------------------------------------------------
#define GM_NKT   (Kdim / 32)        // 24
#define GM_NIT   (2 * GM_NKT)       // 48
#define ASTR     40
#define AROWB    (ASTR * 2)         // 80 bytes
#define GM_ATILE (128 * AROWB)      // 10240
#define GM_STG   (2 * GM_ATILE)     // 20480
#define GM_SMEM  (3 * GM_STG)       // 61440

__global__ __launch_bounds__(256, 2) void gemm_f16x2(
    const __half* __restrict__ A1, const __half* __restrict__ A2,
    const __half* __restrict__ B1,
    const float* __restrict__ bias, float* __restrict__ C, int Nt)
{
    extern __shared__ __align__(16) char gsm[];
    const uint32_t sb = smem_u32(gsm);
    const int tid  = threadIdx.x;
    const int wid  = tid >> 5;
    const int lane = tid & 31;
    const int wm   = wid & 1;        // 0..1 (64-row half)
    const int wn   = wid >> 1;       // 0..3 (32-col quarter)
    const int brow = blockIdx.y * 128;
    const int bcol = blockIdx.x * 128;

    const uint32_t a_off =
        (uint32_t)(((wm * 64 + (lane & 15)) * ASTR + (lane >> 4) * 8) * 2);
    const uint32_t b_off =
        (uint32_t)(((wn * 32 + (lane & 7) + ((lane >> 4) & 1) * 8) * ASTR
                    + ((lane >> 3) & 1) * 8) * 2);

    float c[4][4][4];
    #pragma unroll
    for (int i = 0; i < 4; ++i)
        #pragma unroll
        for (int j = 0; j < 4; ++j)
            #pragma unroll
            for (int r = 0; r < 4; ++r) c[i][j][r] = 0.f;

    auto load_stage = [&](int s, int i) {
        const int p  = i / GM_NKT;            // 0: Ah, 1: Am
        const int k0 = (i % GM_NKT) * 32;
        const __half* Ap = p ? A2 : A1;
        const uint32_t ab = sb + s * GM_STG;
        const uint32_t bb = ab + GM_ATILE;
        #pragma unroll
        for (int j = 0; j < 2; ++j) {
            const int idx = j * 256 + tid;    // 0..511
            const int row = idx >> 2, c4 = idx & 3;
            cpasync16(ab + row * AROWB + c4 * 16,
                      Ap + (size_t)(brow + row) * Kdim + k0 + c4 * 8);
            cpasync16(bb + row * AROWB + c4 * 16,
                      B1 + (size_t)(bcol + row) * Kdim + k0 + c4 * 8);
        }
        cp_commit();
    };

    load_stage(0, 0);
    load_stage(1, 1);

    int s = 0;
    for (int i = 0; i < GM_NIT; ++i) {
        if (i < GM_NIT - 1) cp_wait1(); else cp_wait0();
        __syncthreads();
        if (i + 2 < GM_NIT) {
            int s2 = s + 2; if (s2 >= 3) s2 -= 3;
            load_stage(s2, i + 2);
        }

        const uint32_t aB = sb + s * GM_STG + a_off;
        const uint32_t bB = sb + s * GM_STG + GM_ATILE + b_off;
        #pragma unroll
        for (int ks = 0; ks < 2; ++ks) {
            uint32_t a[4][4], b[2][4];
            #pragma unroll
            for (int mt = 0; mt < 4; ++mt)
                ldsm4(a[mt], aB + mt * (16 * AROWB) + ks * 32);
            #pragma unroll
            for (int nt2 = 0; nt2 < 2; ++nt2)
                ldsm4(b[nt2], bB + nt2 * (16 * AROWB) + ks * 32);
            #pragma unroll
            for (int mt = 0; mt < 4; ++mt)
                #pragma unroll
                for (int nt = 0; nt < 4; ++nt)
                    mma_f16(c[mt][nt], a[mt],
                            b[nt >> 1][(nt & 1) * 2], b[nt >> 1][(nt & 1) * 2 + 1]);
        }
        if (++s == 3) s = 0;
    }

    #pragma unroll
    for (int mt = 0; mt < 4; ++mt) {
        const int gr = brow + wm * 64 + mt * 16 + (lane >> 2);
        #pragma unroll
        for (int nt = 0; nt < 4; ++nt) {
            const int gc = bcol + wn * 32 + nt * 8 + (lane & 3) * 2;
            const float bx = bias[gc], by = bias[gc + 1];
            float2 o0, o1;
            o0.x = c[mt][nt][0] + bx; o0.y = c[mt][nt][1] + by;
            o1.x = c[mt][nt][2] + bx; o1.y = c[mt][nt][3] + by;
            *(float2*)(C + (size_t)gr * Nt + gc)       = o0;
            *(float2*)(C + (size_t)(gr + 8) * Nt + gc) = o1;
        }
    }
}

// ---------------------------------------------------------------------------
// fp32 -> fp16 hi/mid split (x)
// ---------------------------------------------------------------------------
__global__ void split_f16(const float4* __restrict__ src,
                          __half2* __restrict__ hi,
                          __half2* __restrict__ mid, int n4)
{
    int i = blockIdx.x * blockDim.x + threadIdx.x;
    if (i >= n4) return;
    float4 v = src[i];
    uint32_t h0, m0, h1, m1;
    pack_hm(v.x, v.y, h0, m0);
    pack_hm(v.z, v.w, h1, m1);
    hi[i * 2]      = *(__half2*)&h0;
    hi[i * 2 + 1]  = *(__half2*)&h1;
    mid[i * 2]     = *(__half2*)&m0;
    mid[i * 2 + 1] = *(__half2*)&m1;
}

// ---------------------------------------------------------------------------
// transpose + fp16: W[K][N] -> Th[N][K]
// ---------------------------------------------------------------------------
__global__ void trans_f16(const float* __restrict__ W,
                          __half* __restrict__ Th, int K, int N)
{
    __shared__ float tile[32][33];
    const int kb = blockIdx.y * 32, nb = blockIdx.x * 32;
    const int tx = threadIdx.x, ty = threadIdx.y;
    #pragma unroll
    for (int r = ty; r < 32; r += 8)
        tile[r][tx] = W[(size_t)(kb + r) * N + nb + tx];
    __syncthreads();
    #pragma unroll
    for (int i = ty; i < 32; i += 8)
        Th[(size_t)(nb + i) * K + kb + tx] = __float2half_rn(tile[tx][i]);
}

// ---------------------------------------------------------------------------
// RoPE + split: q,k -> fp16 hi/mid pairs; v -> fp16 single.
// ---------------------------------------------------------------------------
__global__ void rope_split_f16(const float* __restrict__ qkv,
    __half2* __restrict__ Qh, __half2* __restrict__ Qm,
    __half2* __restrict__ Kh, __half2* __restrict__ Km,
    __half2* __restrict__ Vh)
{
    const int total = Bsz * Tlen * Hn * (Dh / 2);
    int idx = blockIdx.x * blockDim.x + threadIdx.x;
    if (idx >= total) return;

    const int i  = idx & 31;
    const int h  = (idx >> 5) % Hn;
    const int bt = idx / (32 * Hn);
    const int t  = bt & (Tlen - 1);

    const float* row = qkv + (size_t)bt * C3;
    const int coff = h * Dh + 2 * i;
    float2 q2 = *(const float2*)(row + coff);
    float2 k2 = *(const float2*)(row + Cdim + coff);
    float2 v2 = *(const float2*)(row + 2 * Cdim + coff);

    const float inv_freq = expf(-(float)i * (9.210340371976184f / 32.0f));
    const float ang = (float)t * inv_freq;
    float s, c;
    sincosf(ang, &s, &c);

    float qx = (q2.x * c - q2.y * s) * QSCALE;
    float qy = (q2.y * c + q2.x * s) * QSCALE;
    float kx = k2.x * c - k2.y * s;
    float ky = k2.y * c + k2.x * s;

    const int bh = (bt >> 10) * Hn + h;
    const size_t o = ((size_t)bh * Tlen + t) * (Dh / 2) + i;

    uint32_t hh, mm;
    pack_hm(qx, qy, hh, mm);
    Qh[o] = *(__half2*)&hh; Qm[o] = *(__half2*)&mm;
    pack_hm(kx, ky, hh, mm);
    Kh[o] = *(__half2*)&hh; Km[o] = *(__half2*)&mm;
    uint32_t vv = pack_h(v2.x, v2.y);
    Vh[o] = *(__half2*)&vv;
}

// ---------------------------------------------------------------------------
// Tensor-core causal flash attention (unchanged from R10).
// ---------------------------------------------------------------------------
#define FA_STR   72
#define FA_ROWB  (FA_STR * 2)
#define FA_ARRB  (64 * FA_ROWB)      // 9216
#define FA_STGB  (3 * FA_ARRB)       // 27648
#define FA_SMEM  (2 * FA_STGB)       // 55296

__global__ __launch_bounds__(256, 1) void flash_mma(
    const __half* __restrict__ Qh, const __half* __restrict__ Qm,
    const __half* __restrict__ Kh, const __half* __restrict__ Km,
    const __half* __restrict__ Vh,
    __half* __restrict__ Yh, __half* __restrict__ Ym)
{
    extern __shared__ __align__(16) char sm_raw[];
    const uint32_t sb = smem_u32(sm_raw);
    const int tid  = threadIdx.x;
    const int wid  = tid >> 5;
    const int lane = tid & 31;
    const int bh   = blockIdx.y;
    const int qt   = 7 - blockIdx.x;
    const size_t bhoff = (size_t)bh * (Tlen * Dh);

    #pragma unroll
    for (int j = 0; j < 8; ++j) {
        const int idx = j * 256 + tid;
        const int arr = idx >> 10;
        const int rem = idx & 1023;
        const int row = rem >> 3, c8 = rem & 7;
        const __half* s = arr ? Qm : Qh;
        cpasync16(sb + arr * (128 * FA_ROWB) + row * FA_ROWB + c8 * 16,
                  s + bhoff + ((size_t)(qt * 128 + row)) * Dh + c8 * 8);
    }
    cp_commit(); cp_wait0(); __syncthreads();

    uint32_t qhf[4][4], qmf[4][4];
    {
        const uint32_t base =
            sb + ((wid * 16 + (lane & 15)) * FA_STR + (lane >> 4) * 8) * 2;
        #pragma unroll
        for (int ks = 0; ks < 4; ++ks) {
            ldsm4(qhf[ks], base + ks * 32);
            ldsm4(qmf[ks], base + ks * 32 + 128 * FA_ROWB);
        }
    }
    __syncthreads();

    float O[8][4];
    #pragma unroll
    for (int n = 0; n < 8; ++n)
        #pragma unroll
        for (int r = 0; r < 4; ++r) O[n][r] = 0.f;
    float m0 = -INFINITY, m1 = -INFINITY, l0 = 0.f, l1 = 0.f;

    const int r0g = qt * 128 + wid * 16 + (lane >> 2);

    const int ntiles = 2 * qt + 2;
    auto load_kv = [&](int s, int kt) {
        const int kbase = kt * 64;
        #pragma unroll
        for (int j = 0; j < 6; ++j) {
            const int idx = j * 256 + tid;
            const int arr = idx >> 9;
            const int rem = idx & 511;
            const int row = rem >> 3, c8 = rem & 7;
            const __half* s4 = (arr == 0) ? Kh : (arr == 1) ? Km : Vh;
            cpasync16(sb + s * FA_STGB + arr * FA_ARRB + row * FA_ROWB + c8 * 16,
                      s4 + bhoff + ((size_t)(kbase + row)) * Dh + c8 * 8);
        }
        cp_commit();
    };
    load_kv(0, 0);
    load_kv(1, 1);

    const uint32_t kb_off = ((lane & 7) + ((lane >> 4) & 1) * 8) * FA_ROWB
                            + ((lane >> 3) & 1) * 16;
    const uint32_t v_off  = (lane & 15) * FA_ROWB + (lane >> 4) * 16;

    for (int kt = 0; kt < ntiles; ++kt) {
        const int s = kt & 1;
        if (kt + 2 <= ntiles) cp_wait1(); else cp_wait0();
        __syncthreads();

        const uint32_t kh_b = sb + s * FA_STGB;
        const uint32_t km_b = kh_b + FA_ARRB;
        const uint32_t vh_b = kh_b + 2 * FA_ARRB;

        float S[8][4];
        #pragma unroll
        for (int n = 0; n < 8; ++n)
            #pragma unroll
            for (int r = 0; r < 4; ++r) S[n][r] = 0.f;

        #pragma unroll
        for (int ks = 0; ks < 4; ++ks) {
            #pragma unroll
            for (int g = 0; g < 4; ++g) {
                uint32_t b[4];
                ldsm4(b, kh_b + kb_off + g * (16 * FA_ROWB) + ks * 32);
                mma_f16(S[2 * g],     qhf[ks], b[0], b[1]);
                mma_f16(S[2 * g + 1], qhf[ks], b[2], b[3]);
                mma_f16(S[2 * g],     qmf[ks], b[0], b[1]);
                mma_f16(S[2 * g + 1], qmf[ks], b[2], b[3]);
            }
        }
        #pragma unroll
        for (int ks = 0; ks < 4; ++ks) {
            #pragma unroll
            for (int g = 0; g < 4; ++g) {
                uint32_t b[4];
                ldsm4(b, km_b + kb_off + g * (16 * FA_ROWB) + ks * 32);
                mma_f16(S[2 * g],     qhf[ks], b[0], b[1]);
                mma_f16(S[2 * g + 1], qhf[ks], b[2], b[3]);
            }
        }

        const int kbase = kt * 64;
        if (kt >= 2 * qt) {
            #pragma unroll
            for (int n = 0; n < 8; ++n) {
                const int col = kbase + n * 8 + (lane & 3) * 2;
                if (col     > r0g)     S[n][0] = -INFINITY;
                if (col + 1 > r0g)     S[n][1] = -INFINITY;
                if (col     > r0g + 8) S[n][2] = -INFINITY;
                if (col + 1 > r0g + 8) S[n][3] = -INFINITY;
            }
        }

        float ml0 = -INFINITY, ml1 = -INFINITY;
        #pragma unroll
        for (int n = 0; n < 8; ++n) {
            ml0 = fmaxf(ml0, fmaxf(S[n][0], S[n][1]));
            ml1 = fmaxf(ml1, fmaxf(S[n][2], S[n][3]));
        }
        ml0 = fmaxf(ml0, __shfl_xor_sync(0xFFFFFFFF, ml0, 1));
        ml0 = fmaxf(ml0, __shfl_xor_sync(0xFFFFFFFF, ml0, 2));
        ml1 = fmaxf(ml1, __shfl_xor_sync(0xFFFFFFFF, ml1, 1));
        ml1 = fmaxf(ml1, __shfl_xor_sync(0xFFFFFFFF, ml1, 2));

        const float mn0 = fmaxf(m0, ml0);
        const float mn1 = fmaxf(m1, ml1);
        const float a0 = ex2(m0 - mn0);
        const float a1 = ex2(m1 - mn1);
        m0 = mn0; m1 = mn1;
        l0 *= a0; l1 *= a1;
        #pragma unroll
        for (int n = 0; n < 8; ++n) {
            O[n][0] *= a0; O[n][1] *= a0;
            O[n][2] *= a1; O[n][3] *= a1;
        }
        float sum0 = 0.f, sum1 = 0.f;
        #pragma unroll
        for (int n = 0; n < 8; ++n) {
            S[n][0] = ex2(S[n][0] - mn0); sum0 += S[n][0];
            S[n][1] = ex2(S[n][1] - mn0); sum0 += S[n][1];
            S[n][2] = ex2(S[n][2] - mn1); sum1 += S[n][2];
            S[n][3] = ex2(S[n][3] - mn1); sum1 += S[n][3];
        }
        l0 += sum0; l1 += sum1;

        #pragma unroll
        for (int g = 0; g < 4; ++g) {
            uint32_t pa[4], pb[4];
            pack_hm(S[2 * g][0],     S[2 * g][1],     pa[0], pb[0]);
            pack_hm(S[2 * g][2],     S[2 * g][3],     pa[1], pb[1]);
            pack_hm(S[2 * g + 1][0], S[2 * g + 1][1], pa[2], pb[2]);
            pack_hm(S[2 * g + 1][2], S[2 * g + 1][3], pa[3], pb[3]);
            #pragma unroll
            for (int h2 = 0; h2 < 4; ++h2) {
                uint32_t v4[4];
                ldsm4t(v4, vh_b + v_off + g * (16 * FA_ROWB) + h2 * 32);
                mma_f16(O[2 * h2],     pa, v4[0], v4[1]);
                mma_f16(O[2 * h2 + 1], pa, v4[2], v4[3]);
                mma_f16(O[2 * h2],     pb, v4[0], v4[1]);
                mma_f16(O[2 * h2 + 1], pb, v4[2], v4[3]);
            }
        }

        __syncthreads();
        if (kt + 2 < ntiles) load_kv(s, kt + 2);
    }

    l0 += __shfl_xor_sync(0xFFFFFFFF, l0, 1);
    l0 += __shfl_xor_sync(0xFFFFFFFF, l0, 2);
    l1 += __shfl_xor_sync(0xFFFFFFFF, l1, 1);
    l1 += __shfl_xor_sync(0xFFFFFFFF, l1, 2);
    const float inv0 = 1.f / l0, inv1 = 1.f / l1;

    const int b = bh / Hn, h = bh % Hn;
    const size_t base0 = ((size_t)(b * Tlen + r0g)) * Cdim + h * Dh + (lane & 3) * 2;
    const size_t base1 = base0 + (size_t)8 * Cdim;

    #pragma unroll
    for (int n = 0; n < 8; ++n) {
        uint32_t hh, mm;
        pack_hm(O[n][0] * inv0, O[n][1] * inv0, hh, mm);
        *(uint32_t*)(Yh + base0 + n * 8) = hh;
        *(uint32_t*)(Ym + base0 + n * 8) = mm;
        pack_hm(O[n][2] * inv1, O[n][3] * inv1, hh, mm);
        *(uint32_t*)(Yh + base1 + n * 8) = hh;
        *(uint32_t*)(Ym + base1 + n * 8) = mm;
    }
}

// ---------------------------------------------------------------------------
// Launcher
// ---------------------------------------------------------------------------
extern "C" void kernel_launch(void* const* d_in, const int* in_sizes, int n_in,
                              void* d_out, int out_size)
{
    const float* x      = (const float*)d_in[0];
    const float* W_attn = (const float*)d_in[1];
    const float* b_attn = (const float*)d_in[2];
    const float* W_proj = (const float*)d_in[3];
    const float* b_proj = (const float*)d_in[4];
    float* out = (float*)d_out;

    void* p;
    float* qkv;
    __half *xh, *xm, *wah, *wph;
    __half *qh, *qm, *kh, *km, *vh, *yh, *ym;
    cudaGetSymbolAddress(&p, g_qkv); qkv = (float*)p;
    cudaGetSymbolAddress(&p, g_xh);  xh  = (__half*)p;
    cudaGetSymbolAddress(&p, g_xm);  xm  = (__half*)p;
    cudaGetSymbolAddress(&p, g_wah); wah = (__half*)p;
    cudaGetSymbolAddress(&p, g_wph); wph = (__half*)p;
    cudaGetSymbolAddress(&p, g_qh);  qh  = (__half*)p;
    cudaGetSymbolAddress(&p, g_qm);  qm  = (__half*)p;
    cudaGetSymbolAddress(&p, g_kh);  kh  = (__half*)p;
    cudaGetSymbolAddress(&p, g_km);  km  = (__half*)p;
    cudaGetSymbolAddress(&p, g_vh);  vh  = (__half*)p;
    cudaGetSymbolAddress(&p, g_yh);  yh  = (__half*)p;
    cudaGetSymbolAddress(&p, g_ym);  ym  = (__half*)p;

    cudaFuncSetAttribute(gemm_f16x2, cudaFuncAttributeMaxDynamicSharedMemorySize,
                         GM_SMEM);
    cudaFuncSetAttribute(flash_mma, cudaFuncAttributeMaxDynamicSharedMemorySize,
                         FA_SMEM);

    // prep
    {
        const int n4 = BT * Cdim / 4;
        split_f16<<<(n4 + 255) / 256, 256>>>((const float4*)x,
            (__half2*)xh, (__half2*)xm, n4);
        dim3 g1(C3 / 32, Kdim / 32);
        trans_f16<<<g1, dim3(32, 8)>>>(W_attn, wah, Kdim, C3);
        dim3 g2(Cdim / 32, Kdim / 32);
        trans_f16<<<g2, dim3(32, 8)>>>(W_proj, wph, Kdim, Cdim);
    }

    // 1) qkv = x @ W_attn + b_attn
    {
        dim3 grid(C3 / 128, BT / 128);
        gemm_f16x2<<<grid, 256, GM_SMEM>>>(xh, xm, wah, b_attn, qkv, C3);
    }

    // 2) RoPE + fp16 splits
    {
        const int total = Bsz * Tlen * Hn * (Dh / 2);
        rope_split_f16<<<(total + 255) / 256, 256>>>(qkv,
            (__half2*)qh, (__half2*)qm,
            (__half2*)kh, (__half2*)km,
            (__half2*)vh);
    }

    // 3) tensor-core causal flash attention -> yh/ym splits
    {
        dim3 grid(8, BH);
        flash_mma<<<grid, 256, FA_SMEM>>>(qh, qm, kh, km, vh, yh, ym);
    }

    // 4) out = y @ W_proj + b_proj
    {
        dim3 grid(Cdim / 128, BT / 128);
        gemm_f16x2<<<grid, 256, GM_SMEM>>>(yh, ym, wph, b_proj, out, Cdim);
    }
}

// round 12
// speedup vs baseline: 1.0824x; 1.0824x over previous
#include <cuda_runtime.h>
#include <cuda_fp16.h>
#include <math.h>
#include <stdint.h>

#define Bsz   8
#define Tlen  1024
#define Cdim  768
#define Hn    12
#define Dh    64
#define BT    (Bsz * Tlen)     // 8192
#define C3    (3 * Cdim)       // 2304
#define BH    (Bsz * Hn)       // 96
#define Kdim  768

// ---------------- scratch (device globals; no cudaMalloc allowed) ----------
__device__ float g_qkv[BT * C3];

__device__ __half g_xh[BT * Cdim];
__device__ __half g_xm[BT * Cdim];
__device__ __half g_wah[C3 * Cdim];
__device__ __half g_wph[Cdim * Cdim];

__device__ __half g_qh[BH * Tlen * Dh];
__device__ __half g_qm[BH * Tlen * Dh];
__device__ __half g_kh[BH * Tlen * Dh];
__device__ __half g_km[BH * Tlen * Dh];
__device__ __half g_vh[BH * Tlen * Dh];

__device__ __half g_yh[BT * Cdim];
__device__ __half g_ym[BT * Cdim];

// ---------------- PTX helpers ----------------------------------------------
__device__ __forceinline__ uint32_t smem_u32(const void* p) {
    uint32_t a;
    asm("{ .reg .u64 t; cvta.to.shared.u64 t, %1; cvt.u32.u64 %0, t; }"
        : "=r"(a) : "l"(p));
    return a;
}
__device__ __forceinline__ void cpasync16(uint32_t dst, const void* src) {
    asm volatile("cp.async.cg.shared.global [%0], [%1], 16;\n" :: "r"(dst), "l"(src));
}
__device__ __forceinline__ void cp_commit() {
    asm volatile("cp.async.commit_group;\n" ::: "memory");
}
__device__ __forceinline__ void cp_wait1() {
    asm volatile("cp.async.wait_group 1;\n" ::: "memory");
}
__device__ __forceinline__ void cp_wait0() {
    asm volatile("cp.async.wait_group 0;\n" ::: "memory");
}
__device__ __forceinline__ void ldsm4(uint32_t (&r)[4], uint32_t addr) {
    asm volatile("ldmatrix.sync.aligned.m8n8.x4.shared.b16 {%0,%1,%2,%3}, [%4];"
        : "=r"(r[0]), "=r"(r[1]), "=r"(r[2]), "=r"(r[3]) : "r"(addr));
}
__device__ __forceinline__ void ldsm4t(uint32_t (&r)[4], uint32_t addr) {
    asm volatile("ldmatrix.sync.aligned.m8n8.x4.trans.shared.b16 {%0,%1,%2,%3}, [%4];"
        : "=r"(r[0]), "=r"(r[1]), "=r"(r[2]), "=r"(r[3]) : "r"(addr));
}
__device__ __forceinline__ void mma_f16(float (&c)[4], const uint32_t (&a)[4],
                                        uint32_t b0, uint32_t b1) {
    asm volatile(
        "mma.sync.aligned.m16n8k16.row.col.f32.f16.f16.f32 "
        "{%0,%1,%2,%3}, {%4,%5,%6,%7}, {%8,%9}, {%0,%1,%2,%3};"
        : "+f"(c[0]), "+f"(c[1]), "+f"(c[2]), "+f"(c[3])
        : "r"(a[0]), "r"(a[1]), "r"(a[2]), "r"(a[3]), "r"(b0), "r"(b1));
}
__device__ __forceinline__ float ex2(float x) {
    float y;
    asm("ex2.approx.f32 %0, %1;" : "=f"(y) : "f"(x));
    return y;
}
__device__ __forceinline__ void pack_hm(float p0, float p1, uint32_t& hi, uint32_t& mid) {
    __half2 h = __floats2half2_rn(p0, p1);
    float r0 = p0 - __half2float(__low2half(h));
    float r1 = p1 - __half2float(__high2half(h));
    __half2 m = __floats2half2_rn(r0, r1);
    hi  = *(uint32_t*)&h;
    mid = *(uint32_t*)&m;
}
__device__ __forceinline__ uint32_t pack_h(float p0, float p1) {
    __half2 h = __floats2half2_rn(p0, p1);
    return *(uint32_t*)&h;
}

#define QSCALE (0.125f * 1.4426950408889634f)

// ---------------------------------------------------------------------------
// fp16x2 GEMM (R10 config — best measured): C = (Ah + Am) @ Bh^T + bias.
// CTA 128x128, 4 warps (warp tile 64x64), K-tile 32, 3-stage ring, 2 CTAs/SM.
// ---------------------------------------------------------------------------
#define GM_NKT   (Kdim / 32)        // 24
#define GM_NIT   (2 * GM_NKT)       // 48
#define ASTR     40
#define AROWB    (ASTR * 2)         // 80 bytes
#define GM_ATILE (128 * AROWB)      // 10240
#define GM_STG   (2 * GM_ATILE)     // 20480
#define GM_SMEM  (3 * GM_STG)       // 61440

__global__ __launch_bounds__(128, 2) void gemm_f16x2(
    const __half* __restrict__ A1, const __half* __restrict__ A2,
    const __half* __restrict__ B1,
    const float* __restrict__ bias, float* __restrict__ C, int Nt)
{
    extern __shared__ __align__(16) char gsm[];
    const uint32_t sb = smem_u32(gsm);
    const int tid  = threadIdx.x;
    const int wid  = tid >> 5;
    const int lane = tid & 31;
    const int wm   = wid & 1;
    const int wn   = wid >> 1;
    const int brow = blockIdx.y * 128;
    const int bcol = blockIdx.x * 128;

    const uint32_t a_off =
        (uint32_t)(((wm * 64 + (lane & 15)) * ASTR + (lane >> 4) * 8) * 2);
    const uint32_t b_off =
        (uint32_t)(((wn * 64 + (lane & 7) + ((lane >> 4) & 1) * 8) * ASTR
                    + ((lane >> 3) & 1) * 8) * 2);

    float c[4][8][4];
    #pragma unroll
    for (int i = 0; i < 4; ++i)
        #pragma unroll
        for (int j = 0; j < 8; ++j)
            #pragma unroll
            for (int r = 0; r < 4; ++r) c[i][j][r] = 0.f;

    auto load_stage = [&](int s, int i) {
        const int p  = i / GM_NKT;
        const int k0 = (i % GM_NKT) * 32;
        const __half* Ap = p ? A2 : A1;
        const uint32_t ab = sb + s * GM_STG;
        const uint32_t bb = ab + GM_ATILE;
        #pragma unroll
        for (int j = 0; j < 4; ++j) {
            const int idx = j * 128 + tid;
            const int row = idx >> 2, c4 = idx & 3;
            cpasync16(ab + row * AROWB + c4 * 16,
                      Ap + (size_t)(brow + row) * Kdim + k0 + c4 * 8);
            cpasync16(bb + row * AROWB + c4 * 16,
                      B1 + (size_t)(bcol + row) * Kdim + k0 + c4 * 8);
        }
        cp_commit();
    };

    load_stage(0, 0);
    load_stage(1, 1);

    int s = 0;
    for (int i = 0; i < GM_NIT; ++i) {
        if (i < GM_NIT - 1) cp_wait1(); else cp_wait0();
        __syncthreads();
        if (i + 2 < GM_NIT) {
            int s2 = s + 2; if (s2 >= 3) s2 -= 3;
            load_stage(s2, i + 2);
        }

        const uint32_t aB = sb + s * GM_STG + a_off;
        const uint32_t bB = sb + s * GM_STG + GM_ATILE + b_off;
        #pragma unroll
        for (int ks = 0; ks < 2; ++ks) {
            uint32_t a[4][4], b[4][4];
            #pragma unroll
            for (int mt = 0; mt < 4; ++mt)
                ldsm4(a[mt], aB + mt * (16 * AROWB) + ks * 32);
            #pragma unroll
            for (int nt2 = 0; nt2 < 4; ++nt2)
                ldsm4(b[nt2], bB + nt2 * (16 * AROWB) + ks * 32);
            #pragma unroll
            for (int mt = 0; mt < 4; ++mt)
                #pragma unroll
                for (int nt = 0; nt < 8; ++nt)
                    mma_f16(c[mt][nt], a[mt],
                            b[nt >> 1][(nt & 1) * 2], b[nt >> 1][(nt & 1) * 2 + 1]);
        }
        if (++s == 3) s = 0;
    }

    #pragma unroll
    for (int mt = 0; mt < 4; ++mt) {
        const int gr = brow + wm * 64 + mt * 16 + (lane >> 2);
        #pragma unroll
        for (int nt = 0; nt < 8; ++nt) {
            const int gc = bcol + wn * 64 + nt * 8 + (lane & 3) * 2;
            const float bx = bias[gc], by = bias[gc + 1];
            float2 o0, o1;
            o0.x = c[mt][nt][0] + bx; o0.y = c[mt][nt][1] + by;
            o1.x = c[mt][nt][2] + bx; o1.y = c[mt][nt][3] + by;
            *(float2*)(C + (size_t)gr * Nt + gc)       = o0;
            *(float2*)(C + (size_t)(gr + 8) * Nt + gc) = o1;
        }
    }
}

// ---------------------------------------------------------------------------
// Fused prep: one launch does split(x) + transpose(W_attn) + transpose(W_proj)
// Block ranges: [0, NB_SPLIT) split; [NB_SPLIT, +NB_TA) W_attn; then W_proj.
// ---------------------------------------------------------------------------
#define NB_SPLIT ((BT * Cdim / 4 + 255) / 256)           // 6144
#define NB_TA    ((C3 / 32) * (Kdim / 32))               // 72*24 = 1728
#define NB_TP    ((Cdim / 32) * (Kdim / 32))             // 24*24 = 576
#define NB_PREP  (NB_SPLIT + NB_TA + NB_TP)

__global__ __launch_bounds__(256) void prep_all(
    const float4* __restrict__ x4,
    __half2* __restrict__ xh, __half2* __restrict__ xm,
    const float* __restrict__ Wa, __half* __restrict__ Tha,
    const float* __restrict__ Wp, __half* __restrict__ Thp)
{
    const int blk = blockIdx.x;
    const int tid = threadIdx.x;

    if (blk < NB_SPLIT) {
        const int i = blk * 256 + tid;
        const int n4 = BT * Cdim / 4;
        if (i >= n4) return;
        float4 v = x4[i];
        uint32_t h0, m0, h1, m1;
        pack_hm(v.x, v.y, h0, m0);
        pack_hm(v.z, v.w, h1, m1);
        xh[i * 2]      = *(__half2*)&h0;
        xh[i * 2 + 1]  = *(__half2*)&h1;
        xm[i * 2]     = *(__half2*)&m0;
        xm[i * 2 + 1] = *(__half2*)&m1;
        return;
    }

    // transpose sections
    __shared__ float tile[32][33];
    const float* W;
    __half* Th;
    int N, bx;
    if (blk < NB_SPLIT + NB_TA) {
        W = Wa; Th = Tha; N = C3;
        bx = blk - NB_SPLIT;
    } else {
        W = Wp; Th = Thp; N = Cdim;
        bx = blk - NB_SPLIT - NB_TA;
    }
    const int nblk_x = N / 32;
    const int nb = (bx % nblk_x) * 32;
    const int kb = (bx / nblk_x) * 32;
    const int tx = tid & 31, ty = tid >> 5;

    #pragma unroll
    for (int r = ty; r < 32; r += 8)
        tile[r][tx] = W[(size_t)(kb + r) * N + nb + tx];
    __syncthreads();
    #pragma unroll
    for (int i = ty; i < 32; i += 8)
        Th[(size_t)(nb + i) * Kdim + kb + tx] = __float2half_rn(tile[tx][i]);
}

// ---------------------------------------------------------------------------
// RoPE + split: q,k -> fp16 hi/mid pairs; v -> fp16 single.
// ---------------------------------------------------------------------------
__global__ void rope_split_f16(const float* __restrict__ qkv,
    __half2* __restrict__ Qh, __half2* __restrict__ Qm,
    __half2* __restrict__ Kh, __half2* __restrict__ Km,
    __half2* __restrict__ Vh)
{
    const int total = Bsz * Tlen * Hn * (Dh / 2);
    int idx = blockIdx.x * blockDim.x + threadIdx.x;
    if (idx >= total) return;

    const int i  = idx & 31;
    const int h  = (idx >> 5) % Hn;
    const int bt = idx / (32 * Hn);
    const int t  = bt & (Tlen - 1);

    const float* row = qkv + (size_t)bt * C3;
    const int coff = h * Dh + 2 * i;
    float2 q2 = *(const float2*)(row + coff);
    float2 k2 = *(const float2*)(row + Cdim + coff);
    float2 v2 = *(const float2*)(row + 2 * Cdim + coff);

    const float inv_freq = expf(-(float)i * (9.210340371976184f / 32.0f));
    const float ang = (float)t * inv_freq;
    float s, c;
    sincosf(ang, &s, &c);

    float qx = (q2.x * c - q2.y * s) * QSCALE;
    float qy = (q2.y * c + q2.x * s) * QSCALE;
    float kx = k2.x * c - k2.y * s;
    float ky = k2.y * c + k2.x * s;

    const int bh = (bt >> 10) * Hn + h;
    const size_t o = ((size_t)bh * Tlen + t) * (Dh / 2) + i;

    uint32_t hh, mm;
    pack_hm(qx, qy, hh, mm);
    Qh[o] = *(__half2*)&hh; Qm[o] = *(__half2*)&mm;
    pack_hm(kx, ky, hh, mm);
    Kh[o] = *(__half2*)&hh; Km[o] = *(__half2*)&mm;
    uint32_t vv = pack_h(v2.x, v2.y);
    Vh[o] = *(__half2*)&vv;
}

// ---------------------------------------------------------------------------
// Tensor-core causal flash attention. Now 2 CTAs/SM (regs capped at 128).
// QK: 3 products; PV: 2 products; V single fp16.
// ---------------------------------------------------------------------------
#define FA_STR   72
#define FA_ROWB  (FA_STR * 2)
#define FA_ARRB  (64 * FA_ROWB)      // 9216
#define FA_STGB  (3 * FA_ARRB)       // 27648
#define FA_SMEM  (2 * FA_STGB)       // 55296

__global__ __launch_bounds__(256, 2) void flash_mma(
    const __half* __restrict__ Qh, const __half* __restrict__ Qm,
    const __half* __restrict__ Kh, const __half* __restrict__ Km,
    const __half* __restrict__ Vh,
    __half* __restrict__ Yh, __half* __restrict__ Ym)
{
    extern __shared__ __align__(16) char sm_raw[];
    const uint32_t sb = smem_u32(sm_raw);
    const int tid  = threadIdx.x;
    const int wid  = tid >> 5;
    const int lane = tid & 31;
    const int bh   = blockIdx.y;
    const int qt   = 7 - blockIdx.x;
    const size_t bhoff = (size_t)bh * (Tlen * Dh);

    #pragma unroll
    for (int j = 0; j < 8; ++j) {
        const int idx = j * 256 + tid;
        const int arr = idx >> 10;
        const int rem = idx & 1023;
        const int row = rem >> 3, c8 = rem & 7;
        const __half* s = arr ? Qm : Qh;
        cpasync16(sb + arr * (128 * FA_ROWB) + row * FA_ROWB + c8 * 16,
                  s + bhoff + ((size_t)(qt * 128 + row)) * Dh + c8 * 8);
    }
    cp_commit(); cp_wait0(); __syncthreads();

    uint32_t qhf[4][4], qmf[4][4];
    {
        const uint32_t base =
            sb + ((wid * 16 + (lane & 15)) * FA_STR + (lane >> 4) * 8) * 2;
        #pragma unroll
        for (int ks = 0; ks < 4; ++ks) {
            ldsm4(qhf[ks], base + ks * 32);
            ldsm4(qmf[ks], base + ks * 32 + 128 * FA_ROWB);
        }
    }
    __syncthreads();

    float O[8][4];
    #pragma unroll
    for (int n = 0; n < 8; ++n)
        #pragma unroll
        for (int r = 0; r < 4; ++r) O[n][r] = 0.f;
    float m0 = -INFINITY, m1 = -INFINITY, l0 = 0.f, l1 = 0.f;

    const int r0g = qt * 128 + wid * 16 + (lane >> 2);

    const int ntiles = 2 * qt + 2;
    auto load_kv = [&](int s, int kt) {
        const int kbase = kt * 64;
        #pragma unroll
        for (int j = 0; j < 6; ++j) {
            const int idx = j * 256 + tid;
            const int arr = idx >> 9;
            const int rem = idx & 511;
            const int row = rem >> 3, c8 = rem & 7;
            const __half* s4 = (arr == 0) ? Kh : (arr == 1) ? Km : Vh;
            cpasync16(sb + s * FA_STGB + arr * FA_ARRB + row * FA_ROWB + c8 * 16,
                      s4 + bhoff + ((size_t)(kbase + row)) * Dh + c8 * 8);
        }
        cp_commit();
    };
    load_kv(0, 0);
    load_kv(1, 1);

    const uint32_t kb_off = ((lane & 7) + ((lane >> 4) & 1) * 8) * FA_ROWB
                            + ((lane >> 3) & 1) * 16;
    const uint32_t v_off  = (lane & 15) * FA_ROWB + (lane >> 4) * 16;

    for (int kt = 0; kt < ntiles; ++kt) {
        const int s = kt & 1;
        if (kt + 2 <= ntiles) cp_wait1(); else cp_wait0();
        __syncthreads();

        const uint32_t kh_b = sb + s * FA_STGB;
        const uint32_t km_b = kh_b + FA_ARRB;
        const uint32_t vh_b = kh_b + 2 * FA_ARRB;

        float S[8][4];
        #pragma unroll
        for (int n = 0; n < 8; ++n)
            #pragma unroll
            for (int r = 0; r < 4; ++r) S[n][r] = 0.f;

        #pragma unroll
        for (int ks = 0; ks < 4; ++ks) {
            #pragma unroll
            for (int g = 0; g < 4; ++g) {
                uint32_t b[4];
                ldsm4(b, kh_b + kb_off + g * (16 * FA_ROWB) + ks * 32);
                mma_f16(S[2 * g],     qhf[ks], b[0], b[1]);
                mma_f16(S[2 * g + 1], qhf[ks], b[2], b[3]);
                mma_f16(S[2 * g],     qmf[ks], b[0], b[1]);
                mma_f16(S[2 * g + 1], qmf[ks], b[2], b[3]);
            }
        }
        #pragma unroll
        for (int ks = 0; ks < 4; ++ks) {
            #pragma unroll
            for (int g = 0; g < 4; ++g) {
                uint32_t b[4];
                ldsm4(b, km_b + kb_off + g * (16 * FA_ROWB) + ks * 32);
                mma_f16(S[2 * g],     qhf[ks], b[0], b[1]);
                mma_f16(S[2 * g + 1], qhf[ks], b[2], b[3]);
            }
        }

        const int kbase = kt * 64;
        if (kt >= 2 * qt) {
            #pragma unroll
            for (int n = 0; n < 8; ++n) {
                const int col = kbase + n * 8 + (lane & 3) * 2;
                if (col     > r0g)     S[n][0] = -INFINITY;
                if (col + 1 > r0g)     S[n][1] = -INFINITY;
                if (col     > r0g + 8) S[n][2] = -INFINITY;
                if (col + 1 > r0g + 8) S[n][3] = -INFINITY;
            }
        }

        float ml0 = -INFINITY, ml1 = -INFINITY;
        #pragma unroll
        for (int n = 0; n < 8; ++n) {
            ml0 = fmaxf(ml0, fmaxf(S[n][0], S[n][1]));
            ml1 = fmaxf(ml1, fmaxf(S[n][2], S[n][3]));
        }
        ml0 = fmaxf(ml0, __shfl_xor_sync(0xFFFFFFFF, ml0, 1));
        ml0 = fmaxf(ml0, __shfl_xor_sync(0xFFFFFFFF, ml0, 2));
        ml1 = fmaxf(ml1, __shfl_xor_sync(0xFFFFFFFF, ml1, 1));
        ml1 = fmaxf(ml1, __shfl_xor_sync(0xFFFFFFFF, ml1, 2));

        const float mn0 = fmaxf(m0, ml0);
        const float mn1 = fmaxf(m1, ml1);
        const float a0 = ex2(m0 - mn0);
        const float a1 = ex2(m1 - mn1);
        m0 = mn0; m1 = mn1;
        l0 *= a0; l1 *= a1;
        #pragma unroll
        for (int n = 0; n < 8; ++n) {
            O[n][0] *= a0; O[n][1] *= a0;
            O[n][2] *= a1; O[n][3] *= a1;
        }
        float sum0 = 0.f, sum1 = 0.f;
        #pragma unroll
        for (int n = 0; n < 8; ++n) {
            S[n][0] = ex2(S[n][0] - mn0); sum0 += S[n][0];
            S[n][1] = ex2(S[n][1] - mn0); sum0 += S[n][1];
            S[n][2] = ex2(S[n][2] - mn1); sum1 += S[n][2];
            S[n][3] = ex2(S[n][3] - mn1); sum1 += S[n][3];
        }
        l0 += sum0; l1 += sum1;

        #pragma unroll
        for (int g = 0; g < 4; ++g) {
            uint32_t pa[4], pb[4];
            pack_hm(S[2 * g][0],     S[2 * g][1],     pa[0], pb[0]);
            pack_hm(S[2 * g][2],     S[2 * g][3],     pa[1], pb[1]);
            pack_hm(S[2 * g + 1][0], S[2 * g + 1][1], pa[2], pb[2]);
            pack_hm(S[2 * g + 1][2], S[2 * g + 1][3], pa[3], pb[3]);
            #pragma unroll
            for (int h2 = 0; h2 < 4; ++h2) {
                uint32_t v4[4];
                ldsm4t(v4, vh_b + v_off + g * (16 * FA_ROWB) + h2 * 32);
                mma_f16(O[2 * h2],     pa, v4[0], v4[1]);
                mma_f16(O[2 * h2 + 1], pa, v4[2], v4[3]);
                mma_f16(O[2 * h2],     pb, v4[0], v4[1]);
                mma_f16(O[2 * h2 + 1], pb, v4[2], v4[3]);
            }
        }

        __syncthreads();
        if (kt + 2 < ntiles) load_kv(s, kt + 2);
    }

    l0 += __shfl_xor_sync(0xFFFFFFFF, l0, 1);
    l0 += __shfl_xor_sync(0xFFFFFFFF, l0, 2);
    l1 += __shfl_xor_sync(0xFFFFFFFF, l1, 1);
    l1 += __shfl_xor_sync(0xFFFFFFFF, l1, 2);
    const float inv0 = 1.f / l0, inv1 = 1.f / l1;

    const int b = bh / Hn, h = bh % Hn;
    const size_t base0 = ((size_t)(b * Tlen + r0g)) * Cdim + h * Dh + (lane & 3) * 2;
    const size_t base1 = base0 + (size_t)8 * Cdim;

    #pragma unroll
    for (int n = 0; n < 8; ++n) {
        uint32_t hh, mm;
        pack_hm(O[n][0] * inv0, O[n][1] * inv0, hh, mm);
        *(uint32_t*)(Yh + base0 + n * 8) = hh;
        *(uint32_t*)(Ym + base0 + n * 8) = mm;
        pack_hm(O[n][2] * inv1, O[n][3] * inv1, hh, mm);
        *(uint32_t*)(Yh + base1 + n * 8) = hh;
        *(uint32_t*)(Ym + base1 + n * 8) = mm;
    }
}

// ---------------------------------------------------------------------------
// Launcher
// ---------------------------------------------------------------------------
extern "C" void kernel_launch(void* const* d_in, const int* in_sizes, int n_in,
                              void* d_out, int out_size)
{
    const float* x      = (const float*)d_in[0];
    const float* W_attn = (const float*)d_in[1];
    const float* b_attn = (const float*)d_in[2];
    const float* W_proj = (const float*)d_in[3];
    const float* b_proj = (const float*)d_in[4];
    float* out = (float*)d_out;

    void* p;
    float* qkv;
    __half *xh, *xm, *wah, *wph;
    __half *qh, *qm, *kh, *km, *vh, *yh, *ym;
    cudaGetSymbolAddress(&p, g_qkv); qkv = (float*)p;
    cudaGetSymbolAddress(&p, g_xh);  xh  = (__half*)p;
    cudaGetSymbolAddress(&p, g_xm);  xm  = (__half*)p;
    cudaGetSymbolAddress(&p, g_wah); wah = (__half*)p;
    cudaGetSymbolAddress(&p, g_wph); wph = (__half*)p;
    cudaGetSymbolAddress(&p, g_qh);  qh  = (__half*)p;
    cudaGetSymbolAddress(&p, g_qm);  qm  = (__half*)p;
    cudaGetSymbolAddress(&p, g_kh);  kh  = (__half*)p;
    cudaGetSymbolAddress(&p, g_km);  km  = (__half*)p;
    cudaGetSymbolAddress(&p, g_vh);  vh  = (__half*)p;
    cudaGetSymbolAddress(&p, g_yh);  yh  = (__half*)p;
    cudaGetSymbolAddress(&p, g_ym);  ym  = (__half*)p;

    cudaFuncSetAttribute(gemm_f16x2, cudaFuncAttributeMaxDynamicSharedMemorySize,
                         GM_SMEM);
    cudaFuncSetAttribute(flash_mma, cudaFuncAttributeMaxDynamicSharedMemorySize,
                         FA_SMEM);

    // 0) fused prep: split(x) + transpose(W_attn) + transpose(W_proj)
    prep_all<<<NB_PREP, 256>>>((const float4*)x,
        (__half2*)xh, (__half2*)xm, W_attn, wah, W_proj, wph);

    // 1) qkv = x @ W_attn + b_attn
    {
        dim3 grid(C3 / 128, BT / 128);
        gemm_f16x2<<<grid, 128, GM_SMEM>>>(xh, xm, wah, b_attn, qkv, C3);
    }

    // 2) RoPE + fp16 splits
    {
        const int total = Bsz * Tlen * Hn * (Dh / 2);
        rope_split_f16<<<(total + 255) / 256, 256>>>(qkv,
            (__half2*)qh, (__half2*)qm,
            (__half2*)kh, (__half2*)km,
            (__half2*)vh);
    }

    // 3) tensor-core causal flash attention -> yh/ym splits
    {
        dim3 grid(8, BH);
        flash_mma<<<grid, 256, FA_SMEM>>>(qh, qm, kh, km, vh, yh, ym);
    }

    // 4) out = y @ W_proj + b_proj
    {
        dim3 grid(Cdim / 128, BT / 128);
        gemm_f16x2<<<grid, 128, GM_SMEM>>>(yh, ym, wph, b_proj, out, Cdim);
    }
}

// round 13
// speedup vs baseline: 1.1377x; 1.0511x over previous
#include <cuda_runtime.h>
#include <cuda_fp16.h>
#include <math.h>
#include <stdint.h>

#define Bsz   8
#define Tlen  1024
#define Cdim  768
#define Hn    12
#define Dh    64
#define BT    (Bsz * Tlen)     // 8192
#define C3    (3 * Cdim)       // 2304
#define BH    (Bsz * Hn)       // 96
#define Kdim  768

// ---------------- scratch (device globals; no cudaMalloc allowed) ----------
__device__ float g_qkv[BT * C3];

__device__ __half g_xh[BT * Cdim];
__device__ __half g_xm[BT * Cdim];
__device__ __half g_wah[C3 * Cdim];
__device__ __half g_wph[Cdim * Cdim];

__device__ __half g_qh[BH * Tlen * Dh];
__device__ __half g_qm[BH * Tlen * Dh];
__device__ __half g_kh[BH * Tlen * Dh];
__device__ __half g_km[BH * Tlen * Dh];
__device__ __half g_vh[BH * Tlen * Dh];

__device__ __half g_yh[BT * Cdim];
__device__ __half g_ym[BT * Cdim];

// ---------------- PTX helpers ----------------------------------------------
__device__ __forceinline__ uint32_t smem_u32(const void* p) {
    uint32_t a;
    asm("{ .reg .u64 t; cvta.to.shared.u64 t, %1; cvt.u32.u64 %0, t; }"
        : "=r"(a) : "l"(p));
    return a;
}
__device__ __forceinline__ void cpasync16(uint32_t dst, const void* src) {
    asm volatile("cp.async.cg.shared.global [%0], [%1], 16;\n" :: "r"(dst), "l"(src));
}
__device__ __forceinline__ void cp_commit() {
    asm volatile("cp.async.commit_group;\n" ::: "memory");
}
__device__ __forceinline__ void cp_wait1() {
    asm volatile("cp.async.wait_group 1;\n" ::: "memory");
}
__device__ __forceinline__ void cp_wait0() {
    asm volatile("cp.async.wait_group 0;\n" ::: "memory");
}
__device__ __forceinline__ void ldsm4(uint32_t (&r)[4], uint32_t addr) {
    asm volatile("ldmatrix.sync.aligned.m8n8.x4.shared.b16 {%0,%1,%2,%3}, [%4];"
        : "=r"(r[0]), "=r"(r[1]), "=r"(r[2]), "=r"(r[3]) : "r"(addr));
}
__device__ __forceinline__ void ldsm4t(uint32_t (&r)[4], uint32_t addr) {
    asm volatile("ldmatrix.sync.aligned.m8n8.x4.trans.shared.b16 {%0,%1,%2,%3}, [%4];"
        : "=r"(r[0]), "=r"(r[1]), "=r"(r[2]), "=r"(r[3]) : "r"(addr));
}
__device__ __forceinline__ void mma_f16(float (&c)[4], const uint32_t (&a)[4],
                                        uint32_t b0, uint32_t b1) {
    asm volatile(
        "mma.sync.aligned.m16n8k16.row.col.f32.f16.f16.f32 "
        "{%0,%1,%2,%3}, {%4,%5,%6,%7}, {%8,%9}, {%0,%1,%2,%3};"
        : "+f"(c[0]), "+f"(c[1]), "+f"(c[2]), "+f"(c[3])
        : "r"(a[0]), "r"(a[1]), "r"(a[2]), "r"(a[3]), "r"(b0), "r"(b1));
}
__device__ __forceinline__ float ex2(float x) {
    float y;
    asm("ex2.approx.f32 %0, %1;" : "=f"(y) : "f"(x));
    return y;
}
__device__ __forceinline__ void pack_hm(float p0, float p1, uint32_t& hi, uint32_t& mid) {
    __half2 h = __floats2half2_rn(p0, p1);
    float r0 = p0 - __half2float(__low2half(h));
    float r1 = p1 - __half2float(__high2half(h));
    __half2 m = __floats2half2_rn(r0, r1);
    hi  = *(uint32_t*)&h;
    mid = *(uint32_t*)&m;
}
__device__ __forceinline__ uint32_t pack_h(float p0, float p1) {
    __half2 h = __floats2half2_rn(p0, p1);
    return *(uint32_t*)&h;
}

#define QSCALE (0.125f * 1.4426950408889634f)

// ---------------------------------------------------------------------------
// fp16x2 GEMM: C = (Ah [+ Am]) @ Bh^T + bias. CTAs with bcol >= vcol0 do
// only the Ah pass (used for V columns of GEMM1, which round to fp16 anyway).
// CTA 128x128, 4 warps (64x64), K-tile 32, 3-stage ring, 2 CTAs/SM.
// ---------------------------------------------------------------------------
#define GM_NKT   (Kdim / 32)        // 24
#define GM_NIT   (2 * GM_NKT)       // 48
#define ASTR     40
#define AROWB    (ASTR * 2)         // 80 bytes
#define GM_ATILE (128 * AROWB)      // 10240
#define GM_STG   (2 * GM_ATILE)     // 20480
#define GM_SMEM  (3 * GM_STG)       // 61440

__global__ __launch_bounds__(128, 2) void gemm_f16x2(
    const __half* __restrict__ A1, const __half* __restrict__ A2,
    const __half* __restrict__ B1,
    const float* __restrict__ bias, float* __restrict__ C, int Nt, int vcol0)
{
    extern __shared__ __align__(16) char gsm[];
    const uint32_t sb = smem_u32(gsm);
    const int tid  = threadIdx.x;
    const int wid  = tid >> 5;
    const int lane = tid & 31;
    const int wm   = wid & 1;
    const int wn   = wid >> 1;
    const int brow = blockIdx.y * 128;
    const int bcol = blockIdx.x * 128;

    const int nit = (bcol >= vcol0) ? GM_NKT : GM_NIT;

    const uint32_t a_off =
        (uint32_t)(((wm * 64 + (lane & 15)) * ASTR + (lane >> 4) * 8) * 2);
    const uint32_t b_off =
        (uint32_t)(((wn * 64 + (lane & 7) + ((lane >> 4) & 1) * 8) * ASTR
                    + ((lane >> 3) & 1) * 8) * 2);

    float c[4][8][4];
    #pragma unroll
    for (int i = 0; i < 4; ++i)
        #pragma unroll
        for (int j = 0; j < 8; ++j)
            #pragma unroll
            for (int r = 0; r < 4; ++r) c[i][j][r] = 0.f;

    auto load_stage = [&](int s, int i) {
        const int p  = i / GM_NKT;
        const int k0 = (i % GM_NKT) * 32;
        const __half* Ap = p ? A2 : A1;
        const uint32_t ab = sb + s * GM_STG;
        const uint32_t bb = ab + GM_ATILE;
        #pragma unroll
        for (int j = 0; j < 4; ++j) {
            const int idx = j * 128 + tid;
            const int row = idx >> 2, c4 = idx & 3;
            cpasync16(ab + row * AROWB + c4 * 16,
                      Ap + (size_t)(brow + row) * Kdim + k0 + c4 * 8);
            cpasync16(bb + row * AROWB + c4 * 16,
                      B1 + (size_t)(bcol + row) * Kdim + k0 + c4 * 8);
        }
        cp_commit();
    };

    load_stage(0, 0);
    load_stage(1, 1);

    int s = 0;
    for (int i = 0; i < nit; ++i) {
        if (i < nit - 1) cp_wait1(); else cp_wait0();
        __syncthreads();
        if (i + 2 < nit) {
            int s2 = s + 2; if (s2 >= 3) s2 -= 3;
            load_stage(s2, i + 2);
        }

        const uint32_t aB = sb + s * GM_STG + a_off;
        const uint32_t bB = sb + s * GM_STG + GM_ATILE + b_off;
        #pragma unroll
        for (int ks = 0; ks < 2; ++ks) {
            uint32_t a[4][4], b[4][4];
            #pragma unroll
            for (int mt = 0; mt < 4; ++mt)
                ldsm4(a[mt], aB + mt * (16 * AROWB) + ks * 32);
            #pragma unroll
            for (int nt2 = 0; nt2 < 4; ++nt2)
                ldsm4(b[nt2], bB + nt2 * (16 * AROWB) + ks * 32);
            #pragma unroll
            for (int mt = 0; mt < 4; ++mt)
                #pragma unroll
                for (int nt = 0; nt < 8; ++nt)
                    mma_f16(c[mt][nt], a[mt],
                            b[nt >> 1][(nt & 1) * 2], b[nt >> 1][(nt & 1) * 2 + 1]);
        }
        if (++s == 3) s = 0;
    }

    #pragma unroll
    for (int mt = 0; mt < 4; ++mt) {
        const int gr = brow + wm * 64 + mt * 16 + (lane >> 2);
        #pragma unroll
        for (int nt = 0; nt < 8; ++nt) {
            const int gc = bcol + wn * 64 + nt * 8 + (lane & 3) * 2;
            const float bx = bias[gc], by = bias[gc + 1];
            float2 o0, o1;
            o0.x = c[mt][nt][0] + bx; o0.y = c[mt][nt][1] + by;
            o1.x = c[mt][nt][2] + bx; o1.y = c[mt][nt][3] + by;
            *(float2*)(C + (size_t)gr * Nt + gc)       = o0;
            *(float2*)(C + (size_t)(gr + 8) * Nt + gc) = o1;
        }
    }
}

// ---------------------------------------------------------------------------
// Fused prep: split(x) + transpose(W_attn) + transpose(W_proj)
// ---------------------------------------------------------------------------
#define NB_SPLIT ((BT * Cdim / 4 + 255) / 256)           // 6144
#define NB_TA    ((C3 / 32) * (Kdim / 32))               // 1728
#define NB_TP    ((Cdim / 32) * (Kdim / 32))             // 576
#define NB_PREP  (NB_SPLIT + NB_TA + NB_TP)

__global__ __launch_bounds__(256) void prep_all(
    const float4* __restrict__ x4,
    __half2* __restrict__ xh, __half2* __restrict__ xm,
    const float* __restrict__ Wa, __half* __restrict__ Tha,
    const float* __restrict__ Wp, __half* __restrict__ Thp)
{
    const int blk = blockIdx.x;
    const int tid = threadIdx.x;

    if (blk < NB_SPLIT) {
        const int i = blk * 256 + tid;
        const int n4 = BT * Cdim / 4;
        if (i >= n4) return;
        float4 v = x4[i];
        uint32_t h0, m0, h1, m1;
        pack_hm(v.x, v.y, h0, m0);
        pack_hm(v.z, v.w, h1, m1);
        xh[i * 2]      = *(__half2*)&h0;
        xh[i * 2 + 1]  = *(__half2*)&h1;
        xm[i * 2]     = *(__half2*)&m0;
        xm[i * 2 + 1] = *(__half2*)&m1;
        return;
    }

    __shared__ float tile[32][33];
    const float* W;
    __half* Th;
    int N, bx;
    if (blk < NB_SPLIT + NB_TA) {
        W = Wa; Th = Tha; N = C3;
        bx = blk - NB_SPLIT;
    } else {
        W = Wp; Th = Thp; N = Cdim;
        bx = blk - NB_SPLIT - NB_TA;
    }
    const int nblk_x = N / 32;
    const int nb = (bx % nblk_x) * 32;
    const int kb = (bx / nblk_x) * 32;
    const int tx = tid & 31, ty = tid >> 5;

    #pragma unroll
    for (int r = ty; r < 32; r += 8)
        tile[r][tx] = W[(size_t)(kb + r) * N + nb + tx];
    __syncthreads();
    #pragma unroll
    for (int i = ty; i < 32; i += 8)
        Th[(size_t)(nb + i) * Kdim + kb + tx] = __float2half_rn(tile[tx][i]);
}

// ---------------------------------------------------------------------------
// RoPE + split: q,k -> fp16 hi/mid pairs; v -> fp16 single.
// ---------------------------------------------------------------------------
__global__ void rope_split_f16(const float* __restrict__ qkv,
    __half2* __restrict__ Qh, __half2* __restrict__ Qm,
    __half2* __restrict__ Kh, __half2* __restrict__ Km,
    __half2* __restrict__ Vh)
{
    const int total = Bsz * Tlen * Hn * (Dh / 2);
    int idx = blockIdx.x * blockDim.x + threadIdx.x;
    if (idx >= total) return;

    const int i  = idx & 31;
    const int h  = (idx >> 5) % Hn;
    const int bt = idx / (32 * Hn);
    const int t  = bt & (Tlen - 1);

    const float* row = qkv + (size_t)bt * C3;
    const int coff = h * Dh + 2 * i;
    float2 q2 = *(const float2*)(row + coff);
    float2 k2 = *(const float2*)(row + Cdim + coff);
    float2 v2 = *(const float2*)(row + 2 * Cdim + coff);

    const float inv_freq = expf(-(float)i * (9.210340371976184f / 32.0f));
    const float ang = (float)t * inv_freq;
    float s, c;
    sincosf(ang, &s, &c);

    float qx = (q2.x * c - q2.y * s) * QSCALE;
    float qy = (q2.y * c + q2.x * s) * QSCALE;
    float kx = k2.x * c - k2.y * s;
    float ky = k2.y * c + k2.x * s;

    const int bh = (bt >> 10) * Hn + h;
    const size_t o = ((size_t)bh * Tlen + t) * (Dh / 2) + i;

    uint32_t hh, mm;
    pack_hm(qx, qy, hh, mm);
    Qh[o] = *(__half2*)&hh; Qm[o] = *(__half2*)&mm;
    pack_hm(kx, ky, hh, mm);
    Kh[o] = *(__half2*)&hh; Km[o] = *(__half2*)&mm;
    uint32_t vv = pack_h(v2.x, v2.y);
    Vh[o] = *(__half2*)&vv;
}

// ---------------------------------------------------------------------------
// Tensor-core causal flash attention, 2 CTAs/SM.
// Fully-masked warps skip compute on the upper diagonal tile.
// ---------------------------------------------------------------------------
#define FA_STR   72
#define FA_ROWB  (FA_STR * 2)
#define FA_ARRB  (64 * FA_ROWB)      // 9216
#define FA_STGB  (3 * FA_ARRB)       // 27648
#define FA_SMEM  (2 * FA_STGB)       // 55296

__global__ __launch_bounds__(256, 2) void flash_mma(
    const __half* __restrict__ Qh, const __half* __restrict__ Qm,
    const __half* __restrict__ Kh, const __half* __restrict__ Km,
    const __half* __restrict__ Vh,
    __half* __restrict__ Yh, __half* __restrict__ Ym)
{
    extern __shared__ __align__(16) char sm_raw[];
    const uint32_t sb = smem_u32(sm_raw);
    const int tid  = threadIdx.x;
    const int wid  = tid >> 5;
    const int lane = tid & 31;
    const int bh   = blockIdx.y;
    const int qt   = 7 - blockIdx.x;
    const size_t bhoff = (size_t)bh * (Tlen * Dh);

    #pragma unroll
    for (int j = 0; j < 8; ++j) {
        const int idx = j * 256 + tid;
        const int arr = idx >> 10;
        const int rem = idx & 1023;
        const int row = rem >> 3, c8 = rem & 7;
        const __half* s = arr ? Qm : Qh;
        cpasync16(sb + arr * (128 * FA_ROWB) + row * FA_ROWB + c8 * 16,
                  s + bhoff + ((size_t)(qt * 128 + row)) * Dh + c8 * 8);
    }
    cp_commit(); cp_wait0(); __syncthreads();

    uint32_t qhf[4][4], qmf[4][4];
    {
        const uint32_t base =
            sb + ((wid * 16 + (lane & 15)) * FA_STR + (lane >> 4) * 8) * 2;
        #pragma unroll
        for (int ks = 0; ks < 4; ++ks) {
            ldsm4(qhf[ks], base + ks * 32);
            ldsm4(qmf[ks], base + ks * 32 + 128 * FA_ROWB);
        }
    }
    __syncthreads();

    float O[8][4];
    #pragma unroll
    for (int n = 0; n < 8; ++n)
        #pragma unroll
        for (int r = 0; r < 4; ++r) O[n][r] = 0.f;
    float m0 = -INFINITY, m1 = -INFINITY, l0 = 0.f, l1 = 0.f;

    const int r0g = qt * 128 + wid * 16 + (lane >> 2);
    const int wrow_max = qt * 128 + wid * 16 + 15;

    const int ntiles = 2 * qt + 2;
    auto load_kv = [&](int s, int kt) {
        const int kbase = kt * 64;
        #pragma unroll
        for (int j = 0; j < 6; ++j) {
            const int idx = j * 256 + tid;
            const int arr = idx >> 9;
            const int rem = idx & 511;
            const int row = rem >> 3, c8 = rem & 7;
            const __half* s4 = (arr == 0) ? Kh : (arr == 1) ? Km : Vh;
            cpasync16(sb + s * FA_STGB + arr * FA_ARRB + row * FA_ROWB + c8 * 16,
                      s4 + bhoff + ((size_t)(kbase + row)) * Dh + c8 * 8);
        }
        cp_commit();
    };
    load_kv(0, 0);
    load_kv(1, 1);

    const uint32_t kb_off = ((lane & 7) + ((lane >> 4) & 1) * 8) * FA_ROWB
                            + ((lane >> 3) & 1) * 16;
    const uint32_t v_off  = (lane & 15) * FA_ROWB + (lane >> 4) * 16;

    for (int kt = 0; kt < ntiles; ++kt) {
        const int s = kt & 1;
        if (kt + 2 <= ntiles) cp_wait1(); else cp_wait0();
        __syncthreads();

        const int kbase = kt * 64;
        if (kbase <= wrow_max) {
            const uint32_t kh_b = sb + s * FA_STGB;
            const uint32_t km_b = kh_b + FA_ARRB;
            const uint32_t vh_b = kh_b + 2 * FA_ARRB;

            float S[8][4];
            #pragma unroll
            for (int n = 0; n < 8; ++n)
                #pragma unroll
                for (int r = 0; r < 4; ++r) S[n][r] = 0.f;

            #pragma unroll
            for (int ks = 0; ks < 4; ++ks) {
                #pragma unroll
                for (int g = 0; g < 4; ++g) {
                    uint32_t b[4];
                    ldsm4(b, kh_b + kb_off + g * (16 * FA_ROWB) + ks * 32);
                    mma_f16(S[2 * g],     qhf[ks], b[0], b[1]);
                    mma_f16(S[2 * g + 1], qhf[ks], b[2], b[3]);
                    mma_f16(S[2 * g],     qmf[ks], b[0], b[1]);
                    mma_f16(S[2 * g + 1], qmf[ks], b[2], b[3]);
                }
            }
            #pragma unroll
            for (int ks = 0; ks < 4; ++ks) {
                #pragma unroll
                for (int g = 0; g < 4; ++g) {
                    uint32_t b[4];
                    ldsm4(b, km_b + kb_off + g * (16 * FA_ROWB) + ks * 32);
                    mma_f16(S[2 * g],     qhf[ks], b[0], b[1]);
                    mma_f16(S[2 * g + 1], qhf[ks], b[2], b[3]);
                }
            }

            if (kt >= 2 * qt) {
                #pragma unroll
                for (int n = 0; n < 8; ++n) {
                    const int col = kbase + n * 8 + (lane & 3) * 2;
                    if (col     > r0g)     S[n][0] = -INFINITY;
                    if (col + 1 > r0g)     S[n][1] = -INFINITY;
                    if (col     > r0g + 8) S[n][2] = -INFINITY;
                    if (col + 1 > r0g + 8) S[n][3] = -INFINITY;
                }
            }

            float ml0 = -INFINITY, ml1 = -INFINITY;
            #pragma unroll
            for (int n = 0; n < 8; ++n) {
                ml0 = fmaxf(ml0, fmaxf(S[n][0], S[n][1]));
                ml1 = fmaxf(ml1, fmaxf(S[n][2], S[n][3]));
            }
            ml0 = fmaxf(ml0, __shfl_xor_sync(0xFFFFFFFF, ml0, 1));
            ml0 = fmaxf(ml0, __shfl_xor_sync(0xFFFFFFFF, ml0, 2));
            ml1 = fmaxf(ml1, __shfl_xor_sync(0xFFFFFFFF, ml1, 1));
            ml1 = fmaxf(ml1, __shfl_xor_sync(0xFFFFFFFF, ml1, 2));

            const float mn0 = fmaxf(m0, ml0);
            const float mn1 = fmaxf(m1, ml1);
            const float a0 = ex2(m0 - mn0);
            const float a1 = ex2(m1 - mn1);
            m0 = mn0; m1 = mn1;
            l0 *= a0; l1 *= a1;
            #pragma unroll
            for (int n = 0; n < 8; ++n) {
                O[n][0] *= a0; O[n][1] *= a0;
                O[n][2] *= a1; O[n][3] *= a1;
            }
            float sum0 = 0.f, sum1 = 0.f;
            #pragma unroll
            for (int n = 0; n < 8; ++n) {
                S[n][0] = ex2(S[n][0] - mn0); sum0 += S[n][0];
                S[n][1] = ex2(S[n][1] - mn0); sum0 += S[n][1];
                S[n][2] = ex2(S[n][2] - mn1); sum1 += S[n][2];
                S[n][3] = ex2(S[n][3] - mn1); sum1 += S[n][3];
            }
            l0 += sum0; l1 += sum1;

            #pragma unroll
            for (int g = 0; g < 4; ++g) {
                uint32_t pa[4], pb[4];
                pack_hm(S[2 * g][0],     S[2 * g][1],     pa[0], pb[0]);
                pack_hm(S[2 * g][2],     S[2 * g][3],     pa[1], pb[1]);
                pack_hm(S[2 * g + 1][0], S[2 * g + 1][1], pa[2], pb[2]);
                pack_hm(S[2 * g + 1][2], S[2 * g + 1][3], pa[3], pb[3]);
                #pragma unroll
                for (int h2 = 0; h2 < 4; ++h2) {
                    uint32_t v4[4];
                    ldsm4t(v4, vh_b + v_off + g * (16 * FA_ROWB) + h2 * 32);
                    mma_f16(O[2 * h2],     pa, v4[0], v4[1]);
                    mma_f16(O[2 * h2 + 1], pa, v4[2], v4[3]);
                    mma_f16(O[2 * h2],     pb, v4[0], v4[1]);
                    mma_f16(O[2 * h2 + 1], pb, v4[2], v4[3]);
                }
            }
        }

        __syncthreads();
        if (kt + 2 < ntiles) load_kv(s, kt + 2);
    }

    l0 += __shfl_xor_sync(0xFFFFFFFF, l0, 1);
    l0 += __shfl_xor_sync(0xFFFFFFFF, l0, 2);
    l1 += __shfl_xor_sync(0xFFFFFFFF, l1, 1);
    l1 += __shfl_xor_sync(0xFFFFFFFF, l1, 2);
    const float inv0 = 1.f / l0, inv1 = 1.f / l1;

    const int b = bh / Hn, h = bh % Hn;
    const size_t base0 = ((size_t)(b * Tlen + r0g)) * Cdim + h * Dh + (lane & 3) * 2;
    const size_t base1 = base0 + (size_t)8 * Cdim;

    #pragma unroll
    for (int n = 0; n < 8; ++n) {
        uint32_t hh, mm;
        pack_hm(O[n][0] * inv0, O[n][1] * inv0, hh, mm);
        *(uint32_t*)(Yh + base0 + n * 8) = hh;
        *(uint32_t*)(Ym + base0 + n * 8) = mm;
        pack_hm(O[n][2] * inv1, O[n][3] * inv1, hh, mm);
        *(uint32_t*)(Yh + base1 + n * 8) = hh;
        *(uint32_t*)(Ym + base1 + n * 8) = mm;
    }
}

// ---------------------------------------------------------------------------
// Launcher
// ---------------------------------------------------------------------------
extern "C" void kernel_launch(void* const* d_in, const int* in_sizes, int n_in,
                              void* d_out, int out_size)
{
    const float* x      = (const float*)d_in[0];
    const float* W_attn = (const float*)d_in[1];
    const float* b_attn = (const float*)d_in[2];
    const float* W_proj = (const float*)d_in[3];
    const float* b_proj = (const float*)d_in[4];
    float* out = (float*)d_out;

    void* p;
    float* qkv;
    __half *xh, *xm, *wah, *wph;
    __half *qh, *qm, *kh, *km, *vh, *yh, *ym;
    cudaGetSymbolAddress(&p, g_qkv); qkv = (float*)p;
    cudaGetSymbolAddress(&p, g_xh);  xh  = (__half*)p;
    cudaGetSymbolAddress(&p, g_xm);  xm  = (__half*)p;
    cudaGetSymbolAddress(&p, g_wah); wah = (__half*)p;
    cudaGetSymbolAddress(&p, g_wph); wph = (__half*)p;
    cudaGetSymbolAddress(&p, g_qh);  qh  = (__half*)p;
    cudaGetSymbolAddress(&p, g_qm);  qm  = (__half*)p;
    cudaGetSymbolAddress(&p, g_kh);  kh  = (__half*)p;
    cudaGetSymbolAddress(&p, g_km);  km  = (__half*)p;
    cudaGetSymbolAddress(&p, g_vh);  vh  = (__half*)p;
    cudaGetSymbolAddress(&p, g_yh);  yh  = (__half*)p;
    cudaGetSymbolAddress(&p, g_ym);  ym  = (__half*)p;

    cudaFuncSetAttribute(gemm_f16x2, cudaFuncAttributeMaxDynamicSharedMemorySize,
                         GM_SMEM);
    cudaFuncSetAttribute(flash_mma, cudaFuncAttributeMaxDynamicSharedMemorySize,
                         FA_SMEM);

    // 0) fused prep
    prep_all<<<NB_PREP, 256>>>((const float4*)x,
        (__half2*)xh, (__half2*)xm, W_attn, wah, W_proj, wph);

    // 1) qkv = x @ W_attn + b_attn  (V columns: single pass)
    {
        dim3 grid(C3 / 128, BT / 128);
        gemm_f16x2<<<grid, 128, GM_SMEM>>>(xh, xm, wah, b_attn, qkv, C3,
                                           2 * Cdim);
    }

    // 2) RoPE + fp16 splits
    {
        const int total = Bsz * Tlen * Hn * (Dh / 2);
        rope_split_f16<<<(total + 255) / 256, 256>>>(qkv,
            (__half2*)qh, (__half2*)qm,
            (__half2*)kh, (__half2*)km,
            (__half2*)vh);
    }

    // 3) tensor-core causal flash attention -> yh/ym splits
    {
        dim3 grid(8, BH);
        flash_mma<<<grid, 256, FA_SMEM>>>(qh, qm, kh, km, vh, yh, ym);
    }

    // 4) out = y @ W_proj + b_proj  (always 2 passes)
    {
        dim3 grid(Cdim / 128, BT / 128);
        gemm_f16x2<<<grid, 128, GM_SMEM>>>(yh, ym, wph, b_proj, out, Cdim,
                                           1 << 30);
    }
}

// round 14
// speedup vs baseline: 1.2011x; 1.0557x over previous
#include <cuda_runtime.h>
#include <cuda_fp16.h>
#include <math.h>
#include <stdint.h>

#define Bsz   8
#define Tlen  1024
#define Cdim  768
#define Hn    12
#define Dh    64
#define BT    (Bsz * Tlen)     // 8192
#define C3    (3 * Cdim)       // 2304
#define BH    (Bsz * Hn)       // 96
#define Kdim  768

// ---------------- scratch (device globals; no cudaMalloc allowed) ----------
__device__ float g_qkv[BT * C3];

__device__ __half g_xh[BT * Cdim];
__device__ __half g_xm[BT * Cdim];
__device__ __half g_wah[C3 * Cdim];
__device__ __half g_wph[Cdim * Cdim];

__device__ __half g_qh[BH * Tlen * Dh];
__device__ __half g_qm[BH * Tlen * Dh];
__device__ __half g_kh[BH * Tlen * Dh];
__device__ __half g_km[BH * Tlen * Dh];
__device__ __half g_vh[BH * Tlen * Dh];

__device__ __half g_yh[BT * Cdim];
__device__ __half g_ym[BT * Cdim];

// ---------------- PTX helpers ----------------------------------------------
__device__ __forceinline__ uint32_t smem_u32(const void* p) {
    uint32_t a;
    asm("{ .reg .u64 t; cvta.to.shared.u64 t, %1; cvt.u32.u64 %0, t; }"
        : "=r"(a) : "l"(p));
    return a;
}
__device__ __forceinline__ void cpasync16(uint32_t dst, const void* src) {
    asm volatile("cp.async.cg.shared.global [%0], [%1], 16;\n" :: "r"(dst), "l"(src));
}
__device__ __forceinline__ void cp_commit() {
    asm volatile("cp.async.commit_group;\n" ::: "memory");
}
__device__ __forceinline__ void cp_wait1() {
    asm volatile("cp.async.wait_group 1;\n" ::: "memory");
}
__device__ __forceinline__ void cp_wait0() {
    asm volatile("cp.async.wait_group 0;\n" ::: "memory");
}
__device__ __forceinline__ void ldsm4(uint32_t (&r)[4], uint32_t addr) {
    asm volatile("ldmatrix.sync.aligned.m8n8.x4.shared.b16 {%0,%1,%2,%3}, [%4];"
        : "=r"(r[0]), "=r"(r[1]), "=r"(r[2]), "=r"(r[3]) : "r"(addr));
}
__device__ __forceinline__ void ldsm4t(uint32_t (&r)[4], uint32_t addr) {
    asm volatile("ldmatrix.sync.aligned.m8n8.x4.trans.shared.b16 {%0,%1,%2,%3}, [%4];"
        : "=r"(r[0]), "=r"(r[1]), "=r"(r[2]), "=r"(r[3]) : "r"(addr));
}
__device__ __forceinline__ void mma_f16(float (&c)[4], const uint32_t (&a)[4],
                                        uint32_t b0, uint32_t b1) {
    asm volatile(
        "mma.sync.aligned.m16n8k16.row.col.f32.f16.f16.f32 "
        "{%0,%1,%2,%3}, {%4,%5,%6,%7}, {%8,%9}, {%0,%1,%2,%3};"
        : "+f"(c[0]), "+f"(c[1]), "+f"(c[2]), "+f"(c[3])
        : "r"(a[0]), "r"(a[1]), "r"(a[2]), "r"(a[3]), "r"(b0), "r"(b1));
}
__device__ __forceinline__ float ex2(float x) {
    float y;
    asm("ex2.approx.f32 %0, %1;" : "=f"(y) : "f"(x));
    return y;
}
__device__ __forceinline__ void pack_hm(float p0, float p1, uint32_t& hi, uint32_t& mid) {
    __half2 h = __floats2half2_rn(p0, p1);
    float r0 = p0 - __half2float(__low2half(h));
    float r1 = p1 - __half2float(__high2half(h));
    __half2 m = __floats2half2_rn(r0, r1);
    hi  = *(uint32_t*)&h;
    mid = *(uint32_t*)&m;
}
__device__ __forceinline__ uint32_t pack_h(float p0, float p1) {
    __half2 h = __floats2half2_rn(p0, p1);
    return *(uint32_t*)&h;
}

#define QSCALE (0.125f * 1.4426950408889634f)

// ---------------------------------------------------------------------------
// fp16x2 GEMM: C = (Ah [+ Am]) @ Bh^T + bias. CTAs with bcol >= vcol0 do
// only the Ah pass. CTA 128x128, 4 warps (64x64), K-tile 32, 3-stage ring.
// ---------------------------------------------------------------------------
#define GM_NKT   (Kdim / 32)        // 24
#define GM_NIT   (2 * GM_NKT)       // 48
#define ASTR     40
#define AROWB    (ASTR * 2)         // 80 bytes
#define GM_ATILE (128 * AROWB)      // 10240
#define GM_STG   (2 * GM_ATILE)     // 20480
#define GM_SMEM  (3 * GM_STG)       // 61440

__global__ __launch_bounds__(128, 2) void gemm_f16x2(
    const __half* __restrict__ A1, const __half* __restrict__ A2,
    const __half* __restrict__ B1,
    const float* __restrict__ bias, float* __restrict__ C, int Nt, int vcol0)
{
    extern __shared__ __align__(16) char gsm[];
    const uint32_t sb = smem_u32(gsm);
    const int tid  = threadIdx.x;
    const int wid  = tid >> 5;
    const int lane = tid & 31;
    const int wm   = wid & 1;
    const int wn   = wid >> 1;
    const int brow = blockIdx.y * 128;
    const int bcol = blockIdx.x * 128;

    const int nit = (bcol >= vcol0) ? GM_NKT : GM_NIT;

    const uint32_t a_off =
        (uint32_t)(((wm * 64 + (lane & 15)) * ASTR + (lane >> 4) * 8) * 2);
    const uint32_t b_off =
        (uint32_t)(((wn * 64 + (lane & 7) + ((lane >> 4) & 1) * 8) * ASTR
                    + ((lane >> 3) & 1) * 8) * 2);

    float c[4][8][4];
    #pragma unroll
    for (int i = 0; i < 4; ++i)
        #pragma unroll
        for (int j = 0; j < 8; ++j)
            #pragma unroll
            for (int r = 0; r < 4; ++r) c[i][j][r] = 0.f;

    auto load_stage = [&](int s, int i) {
        const int p  = i / GM_NKT;
        const int k0 = (i % GM_NKT) * 32;
        const __half* Ap = p ? A2 : A1;
        const uint32_t ab = sb + s * GM_STG;
        const uint32_t bb = ab + GM_ATILE;
        #pragma unroll
        for (int j = 0; j < 4; ++j) {
            const int idx = j * 128 + tid;
            const int row = idx >> 2, c4 = idx & 3;
            cpasync16(ab + row * AROWB + c4 * 16,
                      Ap + (size_t)(brow + row) * Kdim + k0 + c4 * 8);
            cpasync16(bb + row * AROWB + c4 * 16,
                      B1 + (size_t)(bcol + row) * Kdim + k0 + c4 * 8);
        }
        cp_commit();
    };

    load_stage(0, 0);
    load_stage(1, 1);

    int s = 0;
    for (int i = 0; i < nit; ++i) {
        if (i < nit - 1) cp_wait1(); else cp_wait0();
        __syncthreads();
        if (i + 2 < nit) {
            int s2 = s + 2; if (s2 >= 3) s2 -= 3;
            load_stage(s2, i + 2);
        }

        const uint32_t aB = sb + s * GM_STG + a_off;
        const uint32_t bB = sb + s * GM_STG + GM_ATILE + b_off;
        #pragma unroll
        for (int ks = 0; ks < 2; ++ks) {
            uint32_t a[4][4], b[4][4];
            #pragma unroll
            for (int mt = 0; mt < 4; ++mt)
                ldsm4(a[mt], aB + mt * (16 * AROWB) + ks * 32);
            #pragma unroll
            for (int nt2 = 0; nt2 < 4; ++nt2)
                ldsm4(b[nt2], bB + nt2 * (16 * AROWB) + ks * 32);
            #pragma unroll
            for (int mt = 0; mt < 4; ++mt)
                #pragma unroll
                for (int nt = 0; nt < 8; ++nt)
                    mma_f16(c[mt][nt], a[mt],
                            b[nt >> 1][(nt & 1) * 2], b[nt >> 1][(nt & 1) * 2 + 1]);
        }
        if (++s == 3) s = 0;
    }

    #pragma unroll
    for (int mt = 0; mt < 4; ++mt) {
        const int gr = brow + wm * 64 + mt * 16 + (lane >> 2);
        #pragma unroll
        for (int nt = 0; nt < 8; ++nt) {
            const int gc = bcol + wn * 64 + nt * 8 + (lane & 3) * 2;
            const float bx = bias[gc], by = bias[gc + 1];
            float2 o0, o1;
            o0.x = c[mt][nt][0] + bx; o0.y = c[mt][nt][1] + by;
            o1.x = c[mt][nt][2] + bx; o1.y = c[mt][nt][3] + by;
            *(float2*)(C + (size_t)gr * Nt + gc)       = o0;
            *(float2*)(C + (size_t)(gr + 8) * Nt + gc) = o1;
        }
    }
}

// ---------------------------------------------------------------------------
// Fused prep: split(x) + transpose(W_attn) + transpose(W_proj)
// ---------------------------------------------------------------------------
#define NB_SPLIT ((BT * Cdim / 4 + 255) / 256)
#define NB_TA    ((C3 / 32) * (Kdim / 32))
#define NB_TP    ((Cdim / 32) * (Kdim / 32))
#define NB_PREP  (NB_SPLIT + NB_TA + NB_TP)

__global__ __launch_bounds__(256) void prep_all(
    const float4* __restrict__ x4,
    __half2* __restrict__ xh, __half2* __restrict__ xm,
    const float* __restrict__ Wa, __half* __restrict__ Tha,
    const float* __restrict__ Wp, __half* __restrict__ Thp)
{
    const int blk = blockIdx.x;
    const int tid = threadIdx.x;

    if (blk < NB_SPLIT) {
        const int i = blk * 256 + tid;
        const int n4 = BT * Cdim / 4;
        if (i >= n4) return;
        float4 v = x4[i];
        uint32_t h0, m0, h1, m1;
        pack_hm(v.x, v.y, h0, m0);
        pack_hm(v.z, v.w, h1, m1);
        xh[i * 2]      = *(__half2*)&h0;
        xh[i * 2 + 1]  = *(__half2*)&h1;
        xm[i * 2]     = *(__half2*)&m0;
        xm[i * 2 + 1] = *(__half2*)&m1;
        return;
    }

    __shared__ float tile[32][33];
    const float* W;
    __half* Th;
    int N, bx;
    if (blk < NB_SPLIT + NB_TA) {
        W = Wa; Th = Tha; N = C3;
        bx = blk - NB_SPLIT;
    } else {
        W = Wp; Th = Thp; N = Cdim;
        bx = blk - NB_SPLIT - NB_TA;
    }
    const int nblk_x = N / 32;
    const int nb = (bx % nblk_x) * 32;
    const int kb = (bx / nblk_x) * 32;
    const int tx = tid & 31, ty = tid >> 5;

    #pragma unroll
    for (int r = ty; r < 32; r += 8)
        tile[r][tx] = W[(size_t)(kb + r) * N + nb + tx];
    __syncthreads();
    #pragma unroll
    for (int i = ty; i < 32; i += 8)
        Th[(size_t)(nb + i) * Kdim + kb + tx] = __float2half_rn(tile[tx][i]);
}

// ---------------------------------------------------------------------------
// RoPE + split: q,k -> fp16 hi/mid pairs; v -> fp16 single.
// ---------------------------------------------------------------------------
__global__ void rope_split_f16(const float* __restrict__ qkv,
    __half2* __restrict__ Qh, __half2* __restrict__ Qm,
    __half2* __restrict__ Kh, __half2* __restrict__ Km,
    __half2* __restrict__ Vh)
{
    const int total = Bsz * Tlen * Hn * (Dh / 2);
    int idx = blockIdx.x * blockDim.x + threadIdx.x;
    if (idx >= total) return;

    const int i  = idx & 31;
    const int h  = (idx >> 5) % Hn;
    const int bt = idx / (32 * Hn);
    const int t  = bt & (Tlen - 1);

    const float* row = qkv + (size_t)bt * C3;
    const int coff = h * Dh + 2 * i;
    float2 q2 = *(const float2*)(row + coff);
    float2 k2 = *(const float2*)(row + Cdim + coff);
    float2 v2 = *(const float2*)(row + 2 * Cdim + coff);

    const float inv_freq = expf(-(float)i * (9.210340371976184f / 32.0f));
    const float ang = (float)t * inv_freq;
    float s, c;
    sincosf(ang, &s, &c);

    float qx = (q2.x * c - q2.y * s) * QSCALE;
    float qy = (q2.y * c + q2.x * s) * QSCALE;
    float kx = k2.x * c - k2.y * s;
    float ky = k2.y * c + k2.x * s;

    const int bh = (bt >> 10) * Hn + h;
    const size_t o = ((size_t)bh * Tlen + t) * (Dh / 2) + i;

    uint32_t hh, mm;
    pack_hm(qx, qy, hh, mm);
    Qh[o] = *(__half2*)&hh; Qm[o] = *(__half2*)&mm;
    pack_hm(kx, ky, hh, mm);
    Kh[o] = *(__half2*)&hh; Km[o] = *(__half2*)&mm;
    uint32_t vv = pack_h(v2.x, v2.y);
    Vh[o] = *(__half2*)&vv;
}

// ---------------------------------------------------------------------------
// Tensor-core causal flash attention, 2 CTAs/SM.
// QK: 3 products. PV: SINGLE product (P fp16). V single fp16.
// ---------------------------------------------------------------------------
#define FA_STR   72
#define FA_ROWB  (FA_STR * 2)
#define FA_ARRB  (64 * FA_ROWB)      // 9216
#define FA_STGB  (3 * FA_ARRB)       // 27648
#define FA_SMEM  (2 * FA_STGB)       // 55296

__global__ __launch_bounds__(256, 2) void flash_mma(
    const __half* __restrict__ Qh, const __half* __restrict__ Qm,
    const __half* __restrict__ Kh, const __half* __restrict__ Km,
    const __half* __restrict__ Vh,
    __half* __restrict__ Yh, __half* __restrict__ Ym)
{
    extern __shared__ __align__(16) char sm_raw[];
    const uint32_t sb = smem_u32(sm_raw);
    const int tid  = threadIdx.x;
    const int wid  = tid >> 5;
    const int lane = tid & 31;
    const int bh   = blockIdx.y;
    const int qt   = 7 - blockIdx.x;
    const size_t bhoff = (size_t)bh * (Tlen * Dh);

    #pragma unroll
    for (int j = 0; j < 8; ++j) {
        const int idx = j * 256 + tid;
        const int arr = idx >> 10;
        const int rem = idx & 1023;
        const int row = rem >> 3, c8 = rem & 7;
        const __half* s = arr ? Qm : Qh;
        cpasync16(sb + arr * (128 * FA_ROWB) + row * FA_ROWB + c8 * 16,
                  s + bhoff + ((size_t)(qt * 128 + row)) * Dh + c8 * 8);
    }
    cp_commit(); cp_wait0(); __syncthreads();

    uint32_t qhf[4][4], qmf[4][4];
    {
        const uint32_t base =
            sb + ((wid * 16 + (lane & 15)) * FA_STR + (lane >> 4) * 8) * 2;
        #pragma unroll
        for (int ks = 0; ks < 4; ++ks) {
            ldsm4(qhf[ks], base + ks * 32);
            ldsm4(qmf[ks], base + ks * 32 + 128 * FA_ROWB);
        }
    }
    __syncthreads();

    float O[8][4];
    #pragma unroll
    for (int n = 0; n < 8; ++n)
        #pragma unroll
        for (int r = 0; r < 4; ++r) O[n][r] = 0.f;
    float m0 = -INFINITY, m1 = -INFINITY, l0 = 0.f, l1 = 0.f;

    const int r0g = qt * 128 + wid * 16 + (lane >> 2);
    const int wrow_max = qt * 128 + wid * 16 + 15;

    const int ntiles = 2 * qt + 2;
    auto load_kv = [&](int s, int kt) {
        const int kbase = kt * 64;
        #pragma unroll
        for (int j = 0; j < 6; ++j) {
            const int idx = j * 256 + tid;
            const int arr = idx >> 9;
            const int rem = idx & 511;
            const int row = rem >> 3, c8 = rem & 7;
            const __half* s4 = (arr == 0) ? Kh : (arr == 1) ? Km : Vh;
            cpasync16(sb + s * FA_STGB + arr * FA_ARRB + row * FA_ROWB + c8 * 16,
                      s4 + bhoff + ((size_t)(kbase + row)) * Dh + c8 * 8);
        }
        cp_commit();
    };
    load_kv(0, 0);
    load_kv(1, 1);

    const uint32_t kb_off = ((lane & 7) + ((lane >> 4) & 1) * 8) * FA_ROWB
                            + ((lane >> 3) & 1) * 16;
    const uint32_t v_off  = (lane & 15) * FA_ROWB + (lane >> 4) * 16;

    for (int kt = 0; kt < ntiles; ++kt) {
        const int s = kt & 1;
        if (kt + 2 <= ntiles) cp_wait1(); else cp_wait0();
        __syncthreads();

        const int kbase = kt * 64;
        if (kbase <= wrow_max) {
            const uint32_t kh_b = sb + s * FA_STGB;
            const uint32_t km_b = kh_b + FA_ARRB;
            const uint32_t vh_b = kh_b + 2 * FA_ARRB;

            float S[8][4];
            #pragma unroll
            for (int n = 0; n < 8; ++n)
                #pragma unroll
                for (int r = 0; r < 4; ++r) S[n][r] = 0.f;

            #pragma unroll
            for (int ks = 0; ks < 4; ++ks) {
                #pragma unroll
                for (int g = 0; g < 4; ++g) {
                    uint32_t b[4];
                    ldsm4(b, kh_b + kb_off + g * (16 * FA_ROWB) + ks * 32);
                    mma_f16(S[2 * g],     qhf[ks], b[0], b[1]);
                    mma_f16(S[2 * g + 1], qhf[ks], b[2], b[3]);
                    mma_f16(S[2 * g],     qmf[ks], b[0], b[1]);
                    mma_f16(S[2 * g + 1], qmf[ks], b[2], b[3]);
                }
            }
            #pragma unroll
            for (int ks = 0; ks < 4; ++ks) {
                #pragma unroll
                for (int g = 0; g < 4; ++g) {
                    uint32_t b[4];
                    ldsm4(b, km_b + kb_off + g * (16 * FA_ROWB) + ks * 32);
                    mma_f16(S[2 * g],     qhf[ks], b[0], b[1]);
                    mma_f16(S[2 * g + 1], qhf[ks], b[2], b[3]);
                }
            }

            if (kt >= 2 * qt) {
                #pragma unroll
                for (int n = 0; n < 8; ++n) {
                    const int col = kbase + n * 8 + (lane & 3) * 2;
                    if (col     > r0g)     S[n][0] = -INFINITY;
                    if (col + 1 > r0g)     S[n][1] = -INFINITY;
                    if (col     > r0g + 8) S[n][2] = -INFINITY;
                    if (col + 1 > r0g + 8) S[n][3] = -INFINITY;
                }
            }

            float ml0 = -INFINITY, ml1 = -INFINITY;
            #pragma unroll
            for (int n = 0; n < 8; ++n) {
                ml0 = fmaxf(ml0, fmaxf(S[n][0], S[n][1]));
                ml1 = fmaxf(ml1, fmaxf(S[n][2], S[n][3]));
            }
            ml0 = fmaxf(ml0, __shfl_xor_sync(0xFFFFFFFF, ml0, 1));
            ml0 = fmaxf(ml0, __shfl_xor_sync(0xFFFFFFFF, ml0, 2));
            ml1 = fmaxf(ml1, __shfl_xor_sync(0xFFFFFFFF, ml1, 1));
            ml1 = fmaxf(ml1, __shfl_xor_sync(0xFFFFFFFF, ml1, 2));

            const float mn0 = fmaxf(m0, ml0);
            const float mn1 = fmaxf(m1, ml1);
            const float a0 = ex2(m0 - mn0);
            const float a1 = ex2(m1 - mn1);
            m0 = mn0; m1 = mn1;
            l0 *= a0; l1 *= a1;
            #pragma unroll
            for (int n = 0; n < 8; ++n) {
                O[n][0] *= a0; O[n][1] *= a0;
                O[n][2] *= a1; O[n][3] *= a1;
            }
            float sum0 = 0.f, sum1 = 0.f;
            #pragma unroll
            for (int n = 0; n < 8; ++n) {
                S[n][0] = ex2(S[n][0] - mn0); sum0 += S[n][0];
                S[n][1] = ex2(S[n][1] - mn0); sum0 += S[n][1];
                S[n][2] = ex2(S[n][2] - mn1); sum1 += S[n][2];
                S[n][3] = ex2(S[n][3] - mn1); sum1 += S[n][3];
            }
            l0 += sum0; l1 += sum1;

            // O += P(fp16) @ Vh  (single product)
            #pragma unroll
            for (int g = 0; g < 4; ++g) {
                uint32_t pa[4];
                pa[0] = pack_h(S[2 * g][0],     S[2 * g][1]);
                pa[1] = pack_h(S[2 * g][2],     S[2 * g][3]);
                pa[2] = pack_h(S[2 * g + 1][0], S[2 * g + 1][1]);
                pa[3] = pack_h(S[2 * g + 1][2], S[2 * g + 1][3]);
                #pragma unroll
                for (int h2 = 0; h2 < 4; ++h2) {
                    uint32_t v4[4];
                    ldsm4t(v4, vh_b + v_off + g * (16 * FA_ROWB) + h2 * 32);
                    mma_f16(O[2 * h2],     pa, v4[0], v4[1]);
                    mma_f16(O[2 * h2 + 1], pa, v4[2], v4[3]);
                }
            }
        }

        __syncthreads();
        if (kt + 2 < ntiles) load_kv(s, kt + 2);
    }

    l0 += __shfl_xor_sync(0xFFFFFFFF, l0, 1);
    l0 += __shfl_xor_sync(0xFFFFFFFF, l0, 2);
    l1 += __shfl_xor_sync(0xFFFFFFFF, l1, 1);
    l1 += __shfl_xor_sync(0xFFFFFFFF, l1, 2);
    const float inv0 = 1.f / l0, inv1 = 1.f / l1;

    const int b = bh / Hn, h = bh % Hn;
    const size_t base0 = ((size_t)(b * Tlen + r0g)) * Cdim + h * Dh + (lane & 3) * 2;
    const size_t base1 = base0 + (size_t)8 * Cdim;

    #pragma unroll
    for (int n = 0; n < 8; ++n) {
        uint32_t hh, mm;
        pack_hm(O[n][0] * inv0, O[n][1] * inv0, hh, mm);
        *(uint32_t*)(Yh + base0 + n * 8) = hh;
        *(uint32_t*)(Ym + base0 + n * 8) = mm;
        pack_hm(O[n][2] * inv1, O[n][3] * inv1, hh, mm);
        *(uint32_t*)(Yh + base1 + n * 8) = hh;
        *(uint32_t*)(Ym + base1 + n * 8) = mm;
    }
}

// ---------------------------------------------------------------------------
// Launcher
// ---------------------------------------------------------------------------
extern "C" void kernel_launch(void* const* d_in, const int* in_sizes, int n_in,
                              void* d_out, int out_size)
{
    const float* x      = (const float*)d_in[0];
    const float* W_attn = (const float*)d_in[1];
    const float* b_attn = (const float*)d_in[2];
    const float* W_proj = (const float*)d_in[3];
    const float* b_proj = (const float*)d_in[4];
    float* out = (float*)d_out;

    void* p;
    float* qkv;
    __half *xh, *xm, *wah, *wph;
    __half *qh, *qm, *kh, *km, *vh, *yh, *ym;
    cudaGetSymbolAddress(&p, g_qkv); qkv = (float*)p;
    cudaGetSymbolAddress(&p, g_xh);  xh  = (__half*)p;
    cudaGetSymbolAddress(&p, g_xm);  xm  = (__half*)p;
    cudaGetSymbolAddress(&p, g_wah); wah = (__half*)p;
    cudaGetSymbolAddress(&p, g_wph); wph = (__half*)p;
    cudaGetSymbolAddress(&p, g_qh);  qh  = (__half*)p;
    cudaGetSymbolAddress(&p, g_qm);  qm  = (__half*)p;
    cudaGetSymbolAddress(&p, g_kh);  kh  = (__half*)p;
    cudaGetSymbolAddress(&p, g_km);  km  = (__half*)p;
    cudaGetSymbolAddress(&p, g_vh);  vh  = (__half*)p;
    cudaGetSymbolAddress(&p, g_yh);  yh  = (__half*)p;
    cudaGetSymbolAddress(&p, g_ym);  ym  = (__half*)p;

    cudaFuncSetAttribute(gemm_f16x2, cudaFuncAttributeMaxDynamicSharedMemorySize,
                         GM_SMEM);
    cudaFuncSetAttribute(flash_mma, cudaFuncAttributeMaxDynamicSharedMemorySize,
                         FA_SMEM);

    // 0) fused prep
    prep_all<<<NB_PREP, 256>>>((const float4*)x,
        (__half2*)xh, (__half2*)xm, W_attn, wah, W_proj, wph);

    // 1) qkv = x @ W_attn + b_attn  (V columns: single pass)
    {
        dim3 grid(C3 / 128, BT / 128);
        gemm_f16x2<<<grid, 128, GM_SMEM>>>(xh, xm, wah, b_attn, qkv, C3,
                                           2 * Cdim);
    }

    // 2) RoPE + fp16 splits
    {
        const int total = Bsz * Tlen * Hn * (Dh / 2);
        rope_split_f16<<<(total + 255) / 256, 256>>>(qkv,
            (__half2*)qh, (__half2*)qm,
            (__half2*)kh, (__half2*)km,
            (__half2*)vh);
    }

    // 3) tensor-core causal flash attention -> yh/ym splits
    {
        dim3 grid(8, BH);
        flash_mma<<<grid, 256, FA_SMEM>>>(qh, qm, kh, km, vh, yh, ym);
    }

    // 4) out = y @ W_proj + b_proj  (always 2 passes)
    {
        dim3 grid(Cdim / 128, BT / 128);
        gemm_f16x2<<<grid, 128, GM_SMEM>>>(yh, ym, wph, b_proj, out, Cdim,
                                           1 << 30);
    }
}

// round 15
// speedup vs baseline: 1.3369x; 1.1131x over previous
#include <cuda_runtime.h>
#include <cuda_fp16.h>
#include <math.h>
#include <stdint.h>

#define Bsz   8
#define Tlen  1024
#define Cdim  768
#define Hn    12
#define Dh    64
#define BT    (Bsz * Tlen)     // 8192
#define C3    (3 * Cdim)       // 2304
#define BH    (Bsz * Hn)       // 96
#define Kdim  768

// ---------------- scratch (device globals; no cudaMalloc allowed) ----------
__device__ float g_qkv[BT * C3];

__device__ __half g_xh[BT * Cdim];
__device__ __half g_xm[BT * Cdim];
__device__ __half g_wah[C3 * Cdim];
__device__ __half g_wph[Cdim * Cdim];

__device__ __half g_qh[BH * Tlen * Dh];
__device__ __half g_qm[BH * Tlen * Dh];
__device__ __half g_kh[BH * Tlen * Dh];
__device__ __half g_km[BH * Tlen * Dh];
__device__ __half g_vh[BH * Tlen * Dh];

__device__ __half g_yh[BT * Cdim];     // y single fp16 now

// ---------------- PTX helpers ----------------------------------------------
__device__ __forceinline__ uint32_t smem_u32(const void* p) {
    uint32_t a;
    asm("{ .reg .u64 t; cvta.to.shared.u64 t, %1; cvt.u32.u64 %0, t; }"
        : "=r"(a) : "l"(p));
    return a;
}
__device__ __forceinline__ void cpasync16(uint32_t dst, const void* src) {
    asm volatile("cp.async.cg.shared.global [%0], [%1], 16;\n" :: "r"(dst), "l"(src));
}
__device__ __forceinline__ void cp_commit() {
    asm volatile("cp.async.commit_group;\n" ::: "memory");
}
__device__ __forceinline__ void cp_wait1() {
    asm volatile("cp.async.wait_group 1;\n" ::: "memory");
}
__device__ __forceinline__ void cp_wait0() {
    asm volatile("cp.async.wait_group 0;\n" ::: "memory");
}
__device__ __forceinline__ void ldsm4(uint32_t (&r)[4], uint32_t addr) {
    asm volatile("ldmatrix.sync.aligned.m8n8.x4.shared.b16 {%0,%1,%2,%3}, [%4];"
        : "=r"(r[0]), "=r"(r[1]), "=r"(r[2]), "=r"(r[3]) : "r"(addr));
}
__device__ __forceinline__ void ldsm4t(uint32_t (&r)[4], uint32_t addr) {
    asm volatile("ldmatrix.sync.aligned.m8n8.x4.trans.shared.b16 {%0,%1,%2,%3}, [%4];"
        : "=r"(r[0]), "=r"(r[1]), "=r"(r[2]), "=r"(r[3]) : "r"(addr));
}
__device__ __forceinline__ void mma_f16(float (&c)[4], const uint32_t (&a)[4],
                                        uint32_t b0, uint32_t b1) {
    asm volatile(
        "mma.sync.aligned.m16n8k16.row.col.f32.f16.f16.f32 "
        "{%0,%1,%2,%3}, {%4,%5,%6,%7}, {%8,%9}, {%0,%1,%2,%3};"
        : "+f"(c[0]), "+f"(c[1]), "+f"(c[2]), "+f"(c[3])
        : "r"(a[0]), "r"(a[1]), "r"(a[2]), "r"(a[3]), "r"(b0), "r"(b1));
}
__device__ __forceinline__ float ex2(float x) {
    float y;
    asm("ex2.approx.f32 %0, %1;" : "=f"(y) : "f"(x));
    return y;
}
__device__ __forceinline__ void pack_hm(float p0, float p1, uint32_t& hi, uint32_t& mid) {
    __half2 h = __floats2half2_rn(p0, p1);
    float r0 = p0 - __half2float(__low2half(h));
    float r1 = p1 - __half2float(__high2half(h));
    __half2 m = __floats2half2_rn(r0, r1);
    hi  = *(uint32_t*)&h;
    mid = *(uint32_t*)&m;
}
__device__ __forceinline__ uint32_t pack_h(float p0, float p1) {
    __half2 h = __floats2half2_rn(p0, p1);
    return *(uint32_t*)&h;
}

#define QSCALE (0.125f * 1.4426950408889634f)

// ---------------------------------------------------------------------------
// fp16 GEMM: C = (Ah [+ Am]) @ Bh^T + bias. CTAs with bcol >= vcol0 do only
// the Ah pass; vcol0 = 0 makes the whole GEMM single-pass.
// CTA 128x128, 4 warps (64x64), K-tile 32, 3-stage ring, 2 CTAs/SM.
// ---------------------------------------------------------------------------
#define GM_NKT   (Kdim / 32)        // 24
#define GM_NIT   (2 * GM_NKT)       // 48
#define ASTR     40
#define AROWB    (ASTR * 2)         // 80 bytes
#define GM_ATILE (128 * AROWB)      // 10240
#define GM_STG   (2 * GM_ATILE)     // 20480
#define GM_SMEM  (3 * GM_STG)       // 61440

__global__ __launch_bounds__(128, 2) void gemm_f16x2(
    const __half* __restrict__ A1, const __half* __restrict__ A2,
    const __half* __restrict__ B1,
    const float* __restrict__ bias, float* __restrict__ C, int Nt, int vcol0)
{
    extern __shared__ __align__(16) char gsm[];
    const uint32_t sb = smem_u32(gsm);
    const int tid  = threadIdx.x;
    const int wid  = tid >> 5;
    const int lane = tid & 31;
    const int wm   = wid & 1;
    const int wn   = wid >> 1;
    const int brow = blockIdx.y * 128;
    const int bcol = blockIdx.x * 128;

    const int nit = (bcol >= vcol0) ? GM_NKT : GM_NIT;

    const uint32_t a_off =
        (uint32_t)(((wm * 64 + (lane & 15)) * ASTR + (lane >> 4) * 8) * 2);
    const uint32_t b_off =
        (uint32_t)(((wn * 64 + (lane & 7) + ((lane >> 4) & 1) * 8) * ASTR
                    + ((lane >> 3) & 1) * 8) * 2);

    float c[4][8][4];
    #pragma unroll
    for (int i = 0; i < 4; ++i)
        #pragma unroll
        for (int j = 0; j < 8; ++j)
            #pragma unroll
            for (int r = 0; r < 4; ++r) c[i][j][r] = 0.f;

    auto load_stage = [&](int s, int i) {
        const int p  = i / GM_NKT;
        const int k0 = (i % GM_NKT) * 32;
        const __half* Ap = p ? A2 : A1;
        const uint32_t ab = sb + s * GM_STG;
        const uint32_t bb = ab + GM_ATILE;
        #pragma unroll
        for (int j = 0; j < 4; ++j) {
            const int idx = j * 128 + tid;
            const int row = idx >> 2, c4 = idx & 3;
            cpasync16(ab + row * AROWB + c4 * 16,
                      Ap + (size_t)(brow + row) * Kdim + k0 + c4 * 8);
            cpasync16(bb + row * AROWB + c4 * 16,
                      B1 + (size_t)(bcol + row) * Kdim + k0 + c4 * 8);
        }
        cp_commit();
    };

    load_stage(0, 0);
    load_stage(1, 1);

    int s = 0;
    for (int i = 0; i < nit; ++i) {
        if (i < nit - 1) cp_wait1(); else cp_wait0();
        __syncthreads();
        if (i + 2 < nit) {
            int s2 = s + 2; if (s2 >= 3) s2 -= 3;
            load_stage(s2, i + 2);
        }

        const uint32_t aB = sb + s * GM_STG + a_off;
        const uint32_t bB = sb + s * GM_STG + GM_ATILE + b_off;
        #pragma unroll
        for (int ks = 0; ks < 2; ++ks) {
            uint32_t a[4][4], b[4][4];
            #pragma unroll
            for (int mt = 0; mt < 4; ++mt)
                ldsm4(a[mt], aB + mt * (16 * AROWB) + ks * 32);
            #pragma unroll
            for (int nt2 = 0; nt2 < 4; ++nt2)
                ldsm4(b[nt2], bB + nt2 * (16 * AROWB) + ks * 32);
            #pragma unroll
            for (int mt = 0; mt < 4; ++mt)
                #pragma unroll
                for (int nt = 0; nt < 8; ++nt)
                    mma_f16(c[mt][nt], a[mt],
                            b[nt >> 1][(nt & 1) * 2], b[nt >> 1][(nt & 1) * 2 + 1]);
        }
        if (++s == 3) s = 0;
    }

    #pragma unroll
    for (int mt = 0; mt < 4; ++mt) {
        const int gr = brow + wm * 64 + mt * 16 + (lane >> 2);
        #pragma unroll
        for (int nt = 0; nt < 8; ++nt) {
            const int gc = bcol + wn * 64 + nt * 8 + (lane & 3) * 2;
            const float bx = bias[gc], by = bias[gc + 1];
            float2 o0, o1;
            o0.x = c[mt][nt][0] + bx; o0.y = c[mt][nt][1] + by;
            o1.x = c[mt][nt][2] + bx; o1.y = c[mt][nt][3] + by;
            *(float2*)(C + (size_t)gr * Nt + gc)       = o0;
            *(float2*)(C + (size_t)(gr + 8) * Nt + gc) = o1;
        }
    }
}

// ---------------------------------------------------------------------------
// Fused prep: split(x) + transpose(W_attn) + transpose(W_proj)
// ---------------------------------------------------------------------------
#define NB_SPLIT ((BT * Cdim / 4 + 255) / 256)
#define NB_TA    ((C3 / 32) * (Kdim / 32))
#define NB_TP    ((Cdim / 32) * (Kdim / 32))
#define NB_PREP  (NB_SPLIT + NB_TA + NB_TP)

__global__ __launch_bounds__(256) void prep_all(
    const float4* __restrict__ x4,
    __half2* __restrict__ xh, __half2* __restrict__ xm,
    const float* __restrict__ Wa, __half* __restrict__ Tha,
    const float* __restrict__ Wp, __half* __restrict__ Thp)
{
    const int blk = blockIdx.x;
    const int tid = threadIdx.x;

    if (blk < NB_SPLIT) {
        const int i = blk * 256 + tid;
        const int n4 = BT * Cdim / 4;
        if (i >= n4) return;
        float4 v = x4[i];
        uint32_t h0, m0, h1, m1;
        pack_hm(v.x, v.y, h0, m0);
        pack_hm(v.z, v.w, h1, m1);
        xh[i * 2]      = *(__half2*)&h0;
        xh[i * 2 + 1]  = *(__half2*)&h1;
        xm[i * 2]     = *(__half2*)&m0;
        xm[i * 2 + 1] = *(__half2*)&m1;
        return;
    }

    __shared__ float tile[32][33];
    const float* W;
    __half* Th;
    int N, bx;
    if (blk < NB_SPLIT + NB_TA) {
        W = Wa; Th = Tha; N = C3;
        bx = blk - NB_SPLIT;
    } else {
        W = Wp; Th = Thp; N = Cdim;
        bx = blk - NB_SPLIT - NB_TA;
    }
    const int nblk_x = N / 32;
    const int nb = (bx % nblk_x) * 32;
    const int kb = (bx / nblk_x) * 32;
    const int tx = tid & 31, ty = tid >> 5;

    #pragma unroll
    for (int r = ty; r < 32; r += 8)
        tile[r][tx] = W[(size_t)(kb + r) * N + nb + tx];
    __syncthreads();
    #pragma unroll
    for (int i = ty; i < 32; i += 8)
        Th[(size_t)(nb + i) * Kdim + kb + tx] = __float2half_rn(tile[tx][i]);
}

// ---------------------------------------------------------------------------
// RoPE + split: q,k -> fp16 hi/mid pairs; v -> fp16 single.
// ---------------------------------------------------------------------------
__global__ void rope_split_f16(const float* __restrict__ qkv,
    __half2* __restrict__ Qh, __half2* __restrict__ Qm,
    __half2* __restrict__ Kh, __half2* __restrict__ Km,
    __half2* __restrict__ Vh)
{
    const int total = Bsz * Tlen * Hn * (Dh / 2);
    int idx = blockIdx.x * blockDim.x + threadIdx.x;
    if (idx >= total) return;

    const int i  = idx & 31;
    const int h  = (idx >> 5) % Hn;
    const int bt = idx / (32 * Hn);
    const int t  = bt & (Tlen - 1);

    const float* row = qkv + (size_t)bt * C3;
    const int coff = h * Dh + 2 * i;
    float2 q2 = *(const float2*)(row + coff);
    float2 k2 = *(const float2*)(row + Cdim + coff);
    float2 v2 = *(const float2*)(row + 2 * Cdim + coff);

    const float inv_freq = expf(-(float)i * (9.210340371976184f / 32.0f));
    const float ang = (float)t * inv_freq;
    float s, c;
    sincosf(ang, &s, &c);

    float qx = (q2.x * c - q2.y * s) * QSCALE;
    float qy = (q2.y * c + q2.x * s) * QSCALE;
    float kx = k2.x * c - k2.y * s;
    float ky = k2.y * c + k2.x * s;

    const int bh = (bt >> 10) * Hn + h;
    const size_t o = ((size_t)bh * Tlen + t) * (Dh / 2) + i;

    uint32_t hh, mm;
    pack_hm(qx, qy, hh, mm);
    Qh[o] = *(__half2*)&hh; Qm[o] = *(__half2*)&mm;
    pack_hm(kx, ky, hh, mm);
    Kh[o] = *(__half2*)&hh; Km[o] = *(__half2*)&mm;
    uint32_t vv = pack_h(v2.x, v2.y);
    Vh[o] = *(__half2*)&vv;
}

// ---------------------------------------------------------------------------
// Tensor-core causal flash attention, 2 CTAs/SM.
// QK: 3 products. PV: single product. Output: single fp16 (Yh only).
// ---------------------------------------------------------------------------
#define FA_STR   72
#define FA_ROWB  (FA_STR * 2)
#define FA_ARRB  (64 * FA_ROWB)      // 9216
#define FA_STGB  (3 * FA_ARRB)       // 27648
#define FA_SMEM  (2 * FA_STGB)       // 55296

__global__ __launch_bounds__(256, 2) void flash_mma(
    const __half* __restrict__ Qh, const __half* __restrict__ Qm,
    const __half* __restrict__ Kh, const __half* __restrict__ Km,
    const __half* __restrict__ Vh,
    __half* __restrict__ Yh)
{
    extern __shared__ __align__(16) char sm_raw[];
    const uint32_t sb = smem_u32(sm_raw);
    const int tid  = threadIdx.x;
    const int wid  = tid >> 5;
    const int lane = tid & 31;
    const int bh   = blockIdx.y;
    const int qt   = 7 - blockIdx.x;
    const size_t bhoff = (size_t)bh * (Tlen * Dh);

    #pragma unroll
    for (int j = 0; j < 8; ++j) {
        const int idx = j * 256 + tid;
        const int arr = idx >> 10;
        const int rem = idx & 1023;
        const int row = rem >> 3, c8 = rem & 7;
        const __half* s = arr ? Qm : Qh;
        cpasync16(sb + arr * (128 * FA_ROWB) + row * FA_ROWB + c8 * 16,
                  s + bhoff + ((size_t)(qt * 128 + row)) * Dh + c8 * 8);
    }
    cp_commit(); cp_wait0(); __syncthreads();

    uint32_t qhf[4][4], qmf[4][4];
    {
        const uint32_t base =
            sb + ((wid * 16 + (lane & 15)) * FA_STR + (lane >> 4) * 8) * 2;
        #pragma unroll
        for (int ks = 0; ks < 4; ++ks) {
            ldsm4(qhf[ks], base + ks * 32);
            ldsm4(qmf[ks], base + ks * 32 + 128 * FA_ROWB);
        }
    }
    __syncthreads();

    float O[8][4];
    #pragma unroll
    for (int n = 0; n < 8; ++n)
        #pragma unroll
        for (int r = 0; r < 4; ++r) O[n][r] = 0.f;
    float m0 = -INFINITY, m1 = -INFINITY, l0 = 0.f, l1 = 0.f;

    const int r0g = qt * 128 + wid * 16 + (lane >> 2);
    const int wrow_max = qt * 128 + wid * 16 + 15;

    const int ntiles = 2 * qt + 2;
    auto load_kv = [&](int s, int kt) {
        const int kbase = kt * 64;
        #pragma unroll
        for (int j = 0; j < 6; ++j) {
            const int idx = j * 256 + tid;
            const int arr = idx >> 9;
            const int rem = idx & 511;
            const int row = rem >> 3, c8 = rem & 7;
            const __half* s4 = (arr == 0) ? Kh : (arr == 1) ? Km : Vh;
            cpasync16(sb + s * FA_STGB + arr * FA_ARRB + row * FA_ROWB + c8 * 16,
                      s4 + bhoff + ((size_t)(kbase + row)) * Dh + c8 * 8);
        }
        cp_commit();
    };
    load_kv(0, 0);
    load_kv(1, 1);

    const uint32_t kb_off = ((lane & 7) + ((lane >> 4) & 1) * 8) * FA_ROWB
                            + ((lane >> 3) & 1) * 16;
    const uint32_t v_off  = (lane & 15) * FA_ROWB + (lane >> 4) * 16;

    for (int kt = 0; kt < ntiles; ++kt) {
        const int s = kt & 1;
        if (kt + 2 <= ntiles) cp_wait1(); else cp_wait0();
        __syncthreads();

        const int kbase = kt * 64;
        if (kbase <= wrow_max) {
            const uint32_t kh_b = sb + s * FA_STGB;
            const uint32_t km_b = kh_b + FA_ARRB;
            const uint32_t vh_b = kh_b + 2 * FA_ARRB;

            float S[8][4];
            #pragma unroll
            for (int n = 0; n < 8; ++n)
                #pragma unroll
                for (int r = 0; r < 4; ++r) S[n][r] = 0.f;

            #pragma unroll
            for (int ks = 0; ks < 4; ++ks) {
                #pragma unroll
                for (int g = 0; g < 4; ++g) {
                    uint32_t b[4];
                    ldsm4(b, kh_b + kb_off + g * (16 * FA_ROWB) + ks * 32);
                    mma_f16(S[2 * g],     qhf[ks], b[0], b[1]);
                    mma_f16(S[2 * g + 1], qhf[ks], b[2], b[3]);
                    mma_f16(S[2 * g],     qmf[ks], b[0], b[1]);
                    mma_f16(S[2 * g + 1], qmf[ks], b[2], b[3]);
                }
            }
            #pragma unroll
            for (int ks = 0; ks < 4; ++ks) {
                #pragma unroll
                for (int g = 0; g < 4; ++g) {
                    uint32_t b[4];
                    ldsm4(b, km_b + kb_off + g * (16 * FA_ROWB) + ks * 32);
                    mma_f16(S[2 * g],     qhf[ks], b[0], b[1]);
                    mma_f16(S[2 * g + 1], qhf[ks], b[2], b[3]);
                }
            }

            if (kt >= 2 * qt) {
                #pragma unroll
                for (int n = 0; n < 8; ++n) {
                    const int col = kbase + n * 8 + (lane & 3) * 2;
                    if (col     > r0g)     S[n][0] = -INFINITY;
                    if (col + 1 > r0g)     S[n][1] = -INFINITY;
                    if (col     > r0g + 8) S[n][2] = -INFINITY;
                    if (col + 1 > r0g + 8) S[n][3] = -INFINITY;
                }
            }

            float ml0 = -INFINITY, ml1 = -INFINITY;
            #pragma unroll
            for (int n = 0; n < 8; ++n) {
                ml0 = fmaxf(ml0, fmaxf(S[n][0], S[n][1]));
                ml1 = fmaxf(ml1, fmaxf(S[n][2], S[n][3]));
            }
            ml0 = fmaxf(ml0, __shfl_xor_sync(0xFFFFFFFF, ml0, 1));
            ml0 = fmaxf(ml0, __shfl_xor_sync(0xFFFFFFFF, ml0, 2));
            ml1 = fmaxf(ml1, __shfl_xor_sync(0xFFFFFFFF, ml1, 1));
            ml1 = fmaxf(ml1, __shfl_xor_sync(0xFFFFFFFF, ml1, 2));

            const float mn0 = fmaxf(m0, ml0);
            const float mn1 = fmaxf(m1, ml1);
            const float a0 = ex2(m0 - mn0);
            const float a1 = ex2(m1 - mn1);
            m0 = mn0; m1 = mn1;
            l0 *= a0; l1 *= a1;
            #pragma unroll
            for (int n = 0; n < 8; ++n) {
                O[n][0] *= a0; O[n][1] *= a0;
                O[n][2] *= a1; O[n][3] *= a1;
            }
            float sum0 = 0.f, sum1 = 0.f;
            #pragma unroll
            for (int n = 0; n < 8; ++n) {
                S[n][0] = ex2(S[n][0] - mn0); sum0 += S[n][0];
                S[n][1] = ex2(S[n][1] - mn0); sum0 += S[n][1];
                S[n][2] = ex2(S[n][2] - mn1); sum1 += S[n][2];
                S[n][3] = ex2(S[n][3] - mn1); sum1 += S[n][3];
            }
            l0 += sum0; l1 += sum1;

            #pragma unroll
            for (int g = 0; g < 4; ++g) {
                uint32_t pa[4];
                pa[0] = pack_h(S[2 * g][0],     S[2 * g][1]);
                pa[1] = pack_h(S[2 * g][2],     S[2 * g][3]);
                pa[2] = pack_h(S[2 * g + 1][0], S[2 * g + 1][1]);
                pa[3] = pack_h(S[2 * g + 1][2], S[2 * g + 1][3]);
                #pragma unroll
                for (int h2 = 0; h2 < 4; ++h2) {
                    uint32_t v4[4];
                    ldsm4t(v4, vh_b + v_off + g * (16 * FA_ROWB) + h2 * 32);
                    mma_f16(O[2 * h2],     pa, v4[0], v4[1]);
                    mma_f16(O[2 * h2 + 1], pa, v4[2], v4[3]);
                }
            }
        }

        __syncthreads();
        if (kt + 2 < ntiles) load_kv(s, kt + 2);
    }

    l0 += __shfl_xor_sync(0xFFFFFFFF, l0, 1);
    l0 += __shfl_xor_sync(0xFFFFFFFF, l0, 2);
    l1 += __shfl_xor_sync(0xFFFFFFFF, l1, 1);
    l1 += __shfl_xor_sync(0xFFFFFFFF, l1, 2);
    const float inv0 = 1.f / l0, inv1 = 1.f / l1;

    const int b = bh / Hn, h = bh % Hn;
    const size_t base0 = ((size_t)(b * Tlen + r0g)) * Cdim + h * Dh + (lane & 3) * 2;
    const size_t base1 = base0 + (size_t)8 * Cdim;

    #pragma unroll
    for (int n = 0; n < 8; ++n) {
        *(uint32_t*)(Yh + base0 + n * 8) = pack_h(O[n][0] * inv0, O[n][1] * inv0);
        *(uint32_t*)(Yh + base1 + n * 8) = pack_h(O[n][2] * inv1, O[n][3] * inv1);
    }
}

// ---------------------------------------------------------------------------
// Launcher
// ---------------------------------------------------------------------------
extern "C" void kernel_launch(void* const* d_in, const int* in_sizes, int n_in,
                              void* d_out, int out_size)
{
    const float* x      = (const float*)d_in[0];
    const float* W_attn = (const float*)d_in[1];
    const float* b_attn = (const float*)d_in[2];
    const float* W_proj = (const float*)d_in[3];
    const float* b_proj = (const float*)d_in[4];
    float* out = (float*)d_out;

    void* p;
    float* qkv;
    __half *xh, *xm, *wah, *wph;
    __half *qh, *qm, *kh, *km, *vh, *yh;
    cudaGetSymbolAddress(&p, g_qkv); qkv = (float*)p;
    cudaGetSymbolAddress(&p, g_xh);  xh  = (__half*)p;
    cudaGetSymbolAddress(&p, g_xm);  xm  = (__half*)p;
    cudaGetSymbolAddress(&p, g_wah); wah = (__half*)p;
    cudaGetSymbolAddress(&p, g_wph); wph = (__half*)p;
    cudaGetSymbolAddress(&p, g_qh);  qh  = (__half*)p;
    cudaGetSymbolAddress(&p, g_qm);  qm  = (__half*)p;
    cudaGetSymbolAddress(&p, g_kh);  kh  = (__half*)p;
    cudaGetSymbolAddress(&p, g_km);  km  = (__half*)p;
    cudaGetSymbolAddress(&p, g_vh);  vh  = (__half*)p;
    cudaGetSymbolAddress(&p, g_yh);  yh  = (__half*)p;

    cudaFuncSetAttribute(gemm_f16x2, cudaFuncAttributeMaxDynamicSharedMemorySize,
                         GM_SMEM);
    cudaFuncSetAttribute(flash_mma, cudaFuncAttributeMaxDynamicSharedMemorySize,
                         FA_SMEM);

    // 0) fused prep
    prep_all<<<NB_PREP, 256>>>((const float4*)x,
        (__half2*)xh, (__half2*)xm, W_attn, wah, W_proj, wph);

    // 1) qkv = x @ W_attn + b_attn  (V columns: single pass)
    {
        dim3 grid(C3 / 128, BT / 128);
        gemm_f16x2<<<grid, 128, GM_SMEM>>>(xh, xm, wah, b_attn, qkv, C3,
                                           2 * Cdim);
    }

    // 2) RoPE + fp16 splits
    {
        const int total = Bsz * Tlen * Hn * (Dh / 2);
        rope_split_f16<<<(total + 255) / 256, 256>>>(qkv,
            (__half2*)qh, (__half2*)qm,
            (__half2*)kh, (__half2*)km,
            (__half2*)vh);
    }

    // 3) tensor-core causal flash attention -> yh (single fp16)
    {
        dim3 grid(8, BH);
        flash_mma<<<grid, 256, FA_SMEM>>>(qh, qm, kh, km, vh, yh);
    }

    // 4) out = y @ W_proj + b_proj  (single pass: vcol0 = 0)
    {
        dim3 grid(Cdim / 128, BT / 128);
        gemm_f16x2<<<grid, 128, GM_SMEM>>>(yh, yh, wph, b_proj, out, Cdim, 0);
    }
}